// round 2
// baseline (speedup 1.0000x reference)
#include <cuda_runtime.h>
#include <math.h>

// ---------------------------------------------------------------------------
// MemTransformerLMEncoder — fp32 baseline
// Dead-code analysis: the UpdateAttn/ffu/lnu branch and `mem` input do not
// affect (output, new_mem). new_mem = hids[:,1008:1024,:]. OutputAttn's
// [new_mem; hids] keys = 1024 hids keys with keys >=1008 double-weighted.
// ---------------------------------------------------------------------------

#define D_MODEL 1024
#define SEQ     1024
#define BATCH   4
#define NHEAD   16
#define DHEAD   64
#define MROWS   (BATCH*SEQ)       // 4096
#define OUT_MAIN (BATCH*SEQ*D_MODEL)  // 4194304

// Scratch (device globals — no allocation allowed)
__device__ float g_hids0[MROWS*D_MODEL];
__device__ float g_q[MROWS*D_MODEL];
__device__ float g_kv[MROWS*2*D_MODEL];
__device__ float g_attn[MROWS*D_MODEL];
__device__ float g_proj[MROWS*D_MODEL];
__device__ float g_hids[MROWS*D_MODEL];
__device__ float g_outattn[MROWS*D_MODEL];

// ---------------------------------------------------------------------------
// Embedding * sqrt(D) + sinusoidal positional encoding (fp32 path mimics jax)
// ---------------------------------------------------------------------------
__global__ void embed_kernel(const int* __restrict__ data,
                             const float* __restrict__ emb,
                             float* __restrict__ out) {
    int idx = blockIdx.x * 256 + threadIdx.x;   // 0 .. 4194303
    int d  = idx & (D_MODEL - 1);
    int bs = idx >> 10;                          // b*SEQ + s
    int s  = bs & (SEQ - 1);
    int tok = data[bs];
    float freq  = powf(10000.0f, -(float)(d & ~1) * (1.0f / 1024.0f));
    float angle = (float)s * freq;
    float pv = (d & 1) ? cosf(angle) : sinf(angle);
    out[idx] = emb[(size_t)tok * D_MODEL + d] * 32.0f + pv;
}

// ---------------------------------------------------------------------------
// SGEMM: C[M,N] = A[M,K] @ W[K,N] (+ resid).  BM=128 BN=64 BK=16, 256 thr.
// ---------------------------------------------------------------------------
#define BM 128
#define BN 64
#define BK 16

__global__ __launch_bounds__(256)
void sgemm_kernel(const float* __restrict__ A, const float* __restrict__ W,
                  const float* __restrict__ resid, float* __restrict__ C,
                  int M, int N, int K) {
    __shared__ float As[BK][BM];
    __shared__ float Bs[BK][BN];
    int tid = threadIdx.x;
    int row0 = blockIdx.y * BM;
    int col0 = blockIdx.x * BN;
    int tx = tid & 15;       // 0..15 -> 4 cols each
    int ty = tid >> 4;       // 0..15 -> 8 rows each
    float acc[8][4];
    #pragma unroll
    for (int i = 0; i < 8; i++)
        #pragma unroll
        for (int j = 0; j < 4; j++) acc[i][j] = 0.0f;

    for (int k0 = 0; k0 < K; k0 += BK) {
        // Load A tile: 128 rows x 16 k  (512 float4, 2 per thread), transpose to As[k][m]
        #pragma unroll
        for (int i = 0; i < 2; i++) {
            int idx = tid + i * 256;     // 0..511
            int r  = idx >> 2;           // 0..127
            int k4 = (idx & 3) * 4;      // 0,4,8,12
            float4 a = *(const float4*)&A[(size_t)(row0 + r) * K + k0 + k4];
            As[k4 + 0][r] = a.x;
            As[k4 + 1][r] = a.y;
            As[k4 + 2][r] = a.z;
            As[k4 + 3][r] = a.w;
        }
        // Load B tile: 16 k x 64 cols (256 float4, 1 per thread)
        {
            int kk = tid >> 4;           // 0..15
            int c4 = (tid & 15) * 4;     // 0..60
            *(float4*)&Bs[kk][c4] = *(const float4*)&W[(size_t)(k0 + kk) * N + col0 + c4];
        }
        __syncthreads();
        #pragma unroll
        for (int kk = 0; kk < BK; kk++) {
            float af[8], bf[4];
            #pragma unroll
            for (int i = 0; i < 8; i++) af[i] = As[kk][ty * 8 + i];
            #pragma unroll
            for (int j = 0; j < 4; j++) bf[j] = Bs[kk][tx * 4 + j];
            #pragma unroll
            for (int i = 0; i < 8; i++)
                #pragma unroll
                for (int j = 0; j < 4; j++)
                    acc[i][j] += af[i] * bf[j];
        }
        __syncthreads();
    }
    // Epilogue (optional residual add)
    #pragma unroll
    for (int i = 0; i < 8; i++) {
        int r = row0 + ty * 8 + i;
        int c = col0 + tx * 4;
        float4 o;
        o.x = acc[i][0]; o.y = acc[i][1]; o.z = acc[i][2]; o.w = acc[i][3];
        if (resid) {
            float4 rd = *(const float4*)&resid[(size_t)r * N + c];
            o.x += rd.x; o.y += rd.y; o.z += rd.z; o.w += rd.w;
        }
        *(float4*)&C[(size_t)r * N + c] = o;
    }
}

// ---------------------------------------------------------------------------
// Flash attention, fp32.  grid=(S/64, H, B), 64 threads; thread t = query row.
// Q layout [B*S, 1024] cols h*64+d; KV layout [B*S, 2048], k at h*64+d,
// v at 1024+h*64+d.  extraFlag: keys with global index >= 1008 get weight 2
// (duplicated mem keys of OutputAttn).
// ---------------------------------------------------------------------------
__global__ __launch_bounds__(64)
void attn_kernel(const float* __restrict__ Q, const float* __restrict__ KV,
                 float* __restrict__ O, int extraFlag) {
    const int qb = blockIdx.x, h = blockIdx.y, b = blockIdx.z;
    const int t = threadIdx.x;
    const int row = qb * 64 + t;
    __shared__ float Ks[64][64];
    __shared__ float Vs[64][64];

    const float* qptr = Q + ((size_t)(b * SEQ + row)) * D_MODEL + h * DHEAD;
    float4 q[16];
    #pragma unroll
    for (int i = 0; i < 16; i++) q[i] = ((const float4*)qptr)[i];

    float4 o[16];
    #pragma unroll
    for (int i = 0; i < 16; i++) o[i] = make_float4(0.f, 0.f, 0.f, 0.f);
    float m = -INFINITY, l = 0.0f;

    for (int kb = 0; kb < 16; kb++) {
        const float* kptr = KV + ((size_t)(b * SEQ + kb * 64 + t)) * (2 * D_MODEL) + h * DHEAD;
        #pragma unroll
        for (int i = 0; i < 16; i++) ((float4*)Ks[t])[i] = ((const float4*)kptr)[i];
        #pragma unroll
        for (int i = 0; i < 16; i++) ((float4*)Vs[t])[i] = ((const float4*)(kptr + D_MODEL))[i];
        __syncthreads();

        float s[64];
        #pragma unroll
        for (int j = 0; j < 64; j++) {
            float a0 = 0.f;
            #pragma unroll
            for (int i = 0; i < 16; i++) {
                float4 k4 = ((const float4*)Ks[j])[i];
                a0 += q[i].x * k4.x + q[i].y * k4.y + q[i].z * k4.z + q[i].w * k4.w;
            }
            s[j] = a0 * 0.125f;   // SCALE = 1/sqrt(64)
        }
        float bm = m;
        #pragma unroll
        for (int j = 0; j < 64; j++) bm = fmaxf(bm, s[j]);
        float rescale = expf(m - bm);   // expf(-inf)=0 first block
        l *= rescale;
        #pragma unroll
        for (int i = 0; i < 16; i++) {
            o[i].x *= rescale; o[i].y *= rescale; o[i].z *= rescale; o[i].w *= rescale;
        }
        #pragma unroll
        for (int j = 0; j < 64; j++) {
            float p = expf(s[j] - bm);
            if (extraFlag && (kb * 64 + j) >= 1008) p *= 2.0f;
            l += p;
            #pragma unroll
            for (int i = 0; i < 16; i++) {
                float4 v4 = ((const float4*)Vs[j])[i];
                o[i].x += p * v4.x; o[i].y += p * v4.y;
                o[i].z += p * v4.z; o[i].w += p * v4.w;
            }
        }
        m = bm;
        __syncthreads();
    }
    float inv = 1.0f / l;
    float* optr = O + ((size_t)(b * SEQ + row)) * D_MODEL + h * DHEAD;
    #pragma unroll
    for (int i = 0; i < 16; i++) {
        float4 r;
        r.x = o[i].x * inv; r.y = o[i].y * inv; r.z = o[i].z * inv; r.w = o[i].w * inv;
        ((float4*)optr)[i] = r;
    }
}

// ---------------------------------------------------------------------------
// LayerNorm helpers (one block per row, 256 threads, D=1024)
// ---------------------------------------------------------------------------
__device__ __forceinline__ float block_reduce_sum(float val, float* sdata) {
    int t = threadIdx.x;
    #pragma unroll
    for (int off = 16; off > 0; off >>= 1)
        val += __shfl_down_sync(0xffffffff, val, off);
    if ((t & 31) == 0) sdata[t >> 5] = val;
    __syncthreads();
    if (t < 32) {
        float v = (t < 8) ? sdata[t] : 0.0f;
        #pragma unroll
        for (int off = 4; off > 0; off >>= 1)
            v += __shfl_down_sync(0xffffffff, v, off);
        if (t == 0) sdata[0] = v;
    }
    __syncthreads();
    float r = sdata[0];
    __syncthreads();
    return r;
}

__global__ __launch_bounds__(256)
void ln_kernel(const float* __restrict__ x, const float* __restrict__ g,
               const float* __restrict__ bb, float* __restrict__ out) {
    __shared__ float sdata[32];
    int row = blockIdx.x;
    int t = threadIdx.x;
    const float* xr = x + (size_t)row * D_MODEL;
    float v[4];
    #pragma unroll
    for (int i = 0; i < 4; i++) v[i] = xr[t + 256 * i];
    float s = v[0] + v[1] + v[2] + v[3];
    float mu = block_reduce_sum(s, sdata) * (1.0f / 1024.0f);
    float sq = 0.f;
    #pragma unroll
    for (int i = 0; i < 4; i++) { float d0 = v[i] - mu; sq += d0 * d0; }
    float var = block_reduce_sum(sq, sdata) * (1.0f / 1024.0f);
    float inv = 1.0f / sqrtf(var + 1e-5f);
    float* orow = out + (size_t)row * D_MODEL;
    #pragma unroll
    for (int i = 0; i < 4; i++) {
        int c = t + 256 * i;
        orow[c] = (v[i] - mu) * inv * g[c] + bb[c];
    }
}

// a = LN(proj)*g1+b1 ; y = hids + a ; out = LN(y)*g2+b2
__global__ __launch_bounds__(256)
void ln_ln_kernel(const float* __restrict__ proj,
                  const float* __restrict__ g1, const float* __restrict__ b1,
                  const float* __restrict__ hids,
                  const float* __restrict__ g2, const float* __restrict__ b2,
                  float* __restrict__ out) {
    __shared__ float sdata[32];
    int row = blockIdx.x;
    int t = threadIdx.x;
    const float* xr = proj + (size_t)row * D_MODEL;
    const float* hr = hids + (size_t)row * D_MODEL;
    float v[4], hv[4];
    #pragma unroll
    for (int i = 0; i < 4; i++) { v[i] = xr[t + 256 * i]; hv[i] = hr[t + 256 * i]; }
    float s = v[0] + v[1] + v[2] + v[3];
    float mu = block_reduce_sum(s, sdata) * (1.0f / 1024.0f);
    float sq = 0.f;
    #pragma unroll
    for (int i = 0; i < 4; i++) { float d0 = v[i] - mu; sq += d0 * d0; }
    float var = block_reduce_sum(sq, sdata) * (1.0f / 1024.0f);
    float inv = 1.0f / sqrtf(var + 1e-5f);
    float y[4];
    #pragma unroll
    for (int i = 0; i < 4; i++) {
        int c = t + 256 * i;
        y[i] = hv[i] + (v[i] - mu) * inv * g1[c] + b1[c];
    }
    float s2 = y[0] + y[1] + y[2] + y[3];
    float mu2 = block_reduce_sum(s2, sdata) * (1.0f / 1024.0f);
    float sq2 = 0.f;
    #pragma unroll
    for (int i = 0; i < 4; i++) { float d0 = y[i] - mu2; sq2 += d0 * d0; }
    float var2 = block_reduce_sum(sq2, sdata) * (1.0f / 1024.0f);
    float inv2 = 1.0f / sqrtf(var2 + 1e-5f);
    float* orow = out + (size_t)row * D_MODEL;
    #pragma unroll
    for (int i = 0; i < 4; i++) {
        int c = t + 256 * i;
        orow[c] = (y[i] - mu2) * inv2 * g2[c] + b2[c];
    }
}

// new_mem = hids[:, 1008:1024, :]
__global__ void copy_mem_kernel(const float* __restrict__ hids, float* __restrict__ dst) {
    int idx = blockIdx.x * 1024 + threadIdx.x;   // 0 .. 65535
    int b = idx >> 14;              // /(16*1024)
    int rem = idx & 16383;
    int mrow = rem >> 10;
    int d = rem & 1023;
    dst[idx] = hids[((size_t)(b * SEQ + 1008 + mrow)) * D_MODEL + d];
}

// ---------------------------------------------------------------------------
static float* s_hids0   = nullptr;
static float* s_q       = nullptr;
static float* s_kv      = nullptr;
static float* s_attn    = nullptr;
static float* s_proj    = nullptr;
static float* s_hids    = nullptr;
static float* s_outattn = nullptr;

static void resolve_scratch() {
    if (s_hids0) return;
    cudaGetSymbolAddress((void**)&s_hids0,   g_hids0);
    cudaGetSymbolAddress((void**)&s_q,       g_q);
    cudaGetSymbolAddress((void**)&s_kv,      g_kv);
    cudaGetSymbolAddress((void**)&s_attn,    g_attn);
    cudaGetSymbolAddress((void**)&s_proj,    g_proj);
    cudaGetSymbolAddress((void**)&s_hids,    g_hids);
    cudaGetSymbolAddress((void**)&s_outattn, g_outattn);
}

extern "C" void kernel_launch(void* const* d_in, const int* in_sizes, int n_in,
                              void* d_out, int out_size) {
    const int*   data  = (const int*)d_in[0];
    // d_in[1] (mem) is dead code — never used
    const float* emb   = (const float*)d_in[2];
    const float* a_qw  = (const float*)d_in[3];
    const float* a_kvw = (const float*)d_in[4];
    const float* a_ow  = (const float*)d_in[5];
    const float* a_g   = (const float*)d_in[6];
    const float* a_b   = (const float*)d_in[7];
    // d_in[8..15]: u_* / ffu_w / lnu_* — all dead code
    const float* o_qw  = (const float*)d_in[16];
    const float* o_kvw = (const float*)d_in[17];
    const float* o_ow  = (const float*)d_in[18];
    const float* o_g   = (const float*)d_in[19];
    const float* o_b   = (const float*)d_in[20];
    const float* ff2_w = (const float*)d_in[21];
    const float* ln1_g = (const float*)d_in[22];
    const float* ln1_b = (const float*)d_in[23];
    const float* ln2_g = (const float*)d_in[24];
    const float* ln2_b = (const float*)d_in[25];
    float* out = (float*)d_out;

    resolve_scratch();
    float *hids0 = s_hids0, *q = s_q, *kv = s_kv, *attn = s_attn;
    float *proj = s_proj, *hids = s_hids, *outattn = s_outattn;

    dim3 gN1(D_MODEL / BN, MROWS / BM);       // (16, 32)
    dim3 gN2(2 * D_MODEL / BN, MROWS / BM);   // (32, 32)
    dim3 gAtt(SEQ / 64, NHEAD, BATCH);        // (16, 16, 4)

    // hids0 = emb[data]*sqrt(D) + pos
    embed_kernel<<<OUT_MAIN / 256, 256>>>(data, emb, hids0);

    // --- self attention (layer) ---
    sgemm_kernel<<<gN1, 256>>>(hids0, a_qw,  nullptr, q,  MROWS, D_MODEL,     D_MODEL);
    sgemm_kernel<<<gN2, 256>>>(hids0, a_kvw, nullptr, kv, MROWS, 2 * D_MODEL, D_MODEL);
    attn_kernel<<<gAtt, 64>>>(q, kv, attn, 0);
    sgemm_kernel<<<gN1, 256>>>(attn, a_ow, hids0, proj, MROWS, D_MODEL, D_MODEL);
    ln_kernel<<<MROWS, 256>>>(proj, a_g, a_b, hids);

    // new_mem = hids[:,1008:1024,:]
    copy_mem_kernel<<<64, 1024>>>(hids, out + OUT_MAIN);

    // --- OutputAttn: keys = [new_mem; hids] == hids with last-16 double weight ---
    sgemm_kernel<<<gN1, 256>>>(hids, o_qw,  nullptr, q,  MROWS, D_MODEL,     D_MODEL);
    sgemm_kernel<<<gN2, 256>>>(hids, o_kvw, nullptr, kv, MROWS, 2 * D_MODEL, D_MODEL);
    attn_kernel<<<gAtt, 64>>>(q, kv, attn, 1);
    sgemm_kernel<<<gN1, 256>>>(attn, o_ow, hids, proj, MROWS, D_MODEL, D_MODEL);
    // attn_out = LN(proj, o_g, o_b); out_attn = LN(hids + attn_out, ln1)
    ln_ln_kernel<<<MROWS, 256>>>(proj, o_g, o_b, hids, ln1_g, ln1_b, outattn);

    // output = LN(out_attn @ ff2_w + out_attn, ln2)
    sgemm_kernel<<<gN1, 256>>>(outattn, ff2_w, outattn, proj, MROWS, D_MODEL, D_MODEL);
    ln_kernel<<<MROWS, 256>>>(proj, ln2_g, ln2_b, out);
}

// round 3
// speedup vs baseline: 2.7262x; 2.7262x over previous
#include <cuda_runtime.h>
#include <math.h>

// ---------------------------------------------------------------------------
// MemTransformerLMEncoder — tf32 tensor-core version
// Dead code: UpdateAttn branch + `mem` input unused. new_mem = hids[:,1008:1024].
// OutputAttn = 1024-key softmax with keys >=1008 double-weighted.
// All GEMM-shaped work via mma.sync.m16n8k8.tf32; softmax/LN/resid in fp32.
// ---------------------------------------------------------------------------

#define D_MODEL 1024
#define SEQ     1024
#define BATCH   4
#define NHEAD   16
#define DHEAD   64
#define MROWS   (BATCH*SEQ)            // 4096
#define OUT_MAIN (BATCH*SEQ*D_MODEL)   // 4194304

// Scratch (device globals — no allocation allowed)
__device__ float g_hids0[MROWS*D_MODEL];
__device__ float g_q[MROWS*D_MODEL];
__device__ float g_kv[MROWS*2*D_MODEL];
__device__ float g_attn[MROWS*D_MODEL];
__device__ float g_proj[MROWS*D_MODEL];
__device__ float g_hids[MROWS*D_MODEL];
__device__ float g_outattn[MROWS*D_MODEL];
__device__ float g_scores[67108864];   // [B][H][S][S] = 4*16*1024*1024 (256MB)

// ---------------------------------------------------------------------------
// Embedding * sqrt(D) + sinusoidal positional encoding
// ---------------------------------------------------------------------------
__global__ void embed_kernel(const int* __restrict__ data,
                             const float* __restrict__ emb,
                             float* __restrict__ out) {
    int idx = blockIdx.x * 256 + threadIdx.x;
    int d  = idx & (D_MODEL - 1);
    int bs = idx >> 10;
    int s  = bs & (SEQ - 1);
    int tok = data[bs];
    float freq  = powf(10000.0f, -(float)(d & ~1) * (1.0f / 1024.0f));
    float angle = (float)s * freq;
    float pv = (d & 1) ? cosf(angle) : sinf(angle);
    out[idx] = emb[(size_t)tok * D_MODEL + d] * 32.0f + pv;
}

// ---------------------------------------------------------------------------
// tf32 helpers
// ---------------------------------------------------------------------------
__device__ __forceinline__ unsigned f2tf(float f) {
    unsigned u;
    asm("cvt.rna.tf32.f32 %0, %1;" : "=r"(u) : "f"(f));
    return u;
}

__device__ __forceinline__ void mma8(float* c, const unsigned* a, const unsigned* b) {
    asm volatile(
        "mma.sync.aligned.m16n8k8.row.col.f32.tf32.tf32.f32 "
        "{%0,%1,%2,%3}, {%4,%5,%6,%7}, {%8,%9}, {%0,%1,%2,%3};"
        : "+f"(c[0]), "+f"(c[1]), "+f"(c[2]), "+f"(c[3])
        : "r"(a[0]), "r"(a[1]), "r"(a[2]), "r"(a[3]), "r"(b[0]), "r"(b[1]));
}

// ---------------------------------------------------------------------------
// Batched tf32 GEMM: C[M,N] = A[M,K] @ B (+resid)
//   BNMAJ=false: B row-major [K,N] stride ldb (k rows, n contiguous)
//   BNMAJ=true:  B n-major  [N,K] stride ldb (n rows, k contiguous)  => C = A B^T
// Batch z -> (zb, zh) = (z/H2, z%H2); pointer offsets zb*s?1 + zh*s?2.
// BM=128, BK=32, 256 threads, 8 warps (4m x 2n).
// ---------------------------------------------------------------------------
template<int BN, bool BNMAJ>
__global__ __launch_bounds__(256)
void mma_gemm(const float* __restrict__ Ag, const float* __restrict__ Bg,
              const float* __restrict__ resid, float* __restrict__ Cg,
              int K, int lda, int ldb, int ldc,
              long sA1, long sA2, long sB1, long sB2, long sC1, long sC2, int H2) {
    constexpr int BM = 128, BK = 32;
    constexpr int WN = (BN == 128) ? 64 : 32;
    constexpr int NI = WN / 8;     // 8 or 4
    constexpr int MI = 2;
    __shared__ unsigned As[BK][BM + 8];   // stride 136 -> bank = 8k + m
    __shared__ unsigned Bs[BK][BN + 8];   // stride mod 32 == 8 for BN=128/64

    const int z  = blockIdx.z;
    const int zb = z / H2, zh = z % H2;
    const float* A = Ag + (size_t)zb * sA1 + (size_t)zh * sA2;
    const float* B = Bg + (size_t)zb * sB1 + (size_t)zh * sB2;
    float*       C = Cg + (size_t)zb * sC1 + (size_t)zh * sC2;
    const float* R = resid;

    const int tid  = threadIdx.x;
    const int lane = tid & 31, warp = tid >> 5;
    const int row0 = blockIdx.y * BM, col0 = blockIdx.x * BN;
    const int wm = (warp & 3) * 32, wn = (warp >> 2) * WN;

    float acc[MI][NI][4];
    #pragma unroll
    for (int mi = 0; mi < MI; mi++)
        #pragma unroll
        for (int ni = 0; ni < NI; ni++)
            #pragma unroll
            for (int c = 0; c < 4; c++) acc[mi][ni][c] = 0.0f;

    for (int k0 = 0; k0 < K; k0 += BK) {
        // ---- load A tile transposed: As[k][m] = tf32(A[(row0+m)*lda + k0+k])
        {
            int m   = tid & 127;
            int kc0 = (tid >> 7) * 4;    // 0 or 4
            #pragma unroll
            for (int s = 0; s < 4; s++) {
                int kc = kc0 + 8 * s;
                float4 v = *(const float4*)&A[(size_t)(row0 + m) * lda + k0 + kc];
                As[kc + 0][m] = f2tf(v.x);
                As[kc + 1][m] = f2tf(v.y);
                As[kc + 2][m] = f2tf(v.z);
                As[kc + 3][m] = f2tf(v.w);
            }
        }
        // ---- load B tile: Bs[k][n]
        if (BNMAJ) {
            constexpr int G = 256 / BN;
            int n = tid & (BN - 1);
            int g = tid / BN;
            #pragma unroll
            for (int s = 0; s < BK / (4 * G); s++) {
                int kc = 4 * g + 4 * G * s;
                float4 v = *(const float4*)&B[(size_t)(col0 + n) * ldb + k0 + kc];
                Bs[kc + 0][n] = f2tf(v.x);
                Bs[kc + 1][n] = f2tf(v.y);
                Bs[kc + 2][n] = f2tf(v.z);
                Bs[kc + 3][n] = f2tf(v.w);
            }
        } else {
            constexpr int TPR = BN / 4;     // threads per row
            constexpr int RPI = 256 / TPR;  // rows per iteration
            int kk = tid / TPR;
            int nc = (tid % TPR) * 4;
            #pragma unroll
            for (int s = 0; s < BK / RPI; s++) {
                int k = kk + RPI * s;
                float4 v = *(const float4*)&B[(size_t)(k0 + k) * ldb + col0 + nc];
                Bs[k][nc + 0] = f2tf(v.x);
                Bs[k][nc + 1] = f2tf(v.y);
                Bs[k][nc + 2] = f2tf(v.z);
                Bs[k][nc + 3] = f2tf(v.w);
            }
        }
        __syncthreads();

        // ---- compute
        #pragma unroll
        for (int kk = 0; kk < BK; kk += 8) {
            unsigned af[MI][4], bf[NI][2];
            int r = lane & 3, q = lane >> 2;
            #pragma unroll
            for (int mi = 0; mi < MI; mi++) {
                int m = wm + mi * 16 + q;
                af[mi][0] = As[kk + r][m];
                af[mi][1] = As[kk + r][m + 8];
                af[mi][2] = As[kk + r + 4][m];
                af[mi][3] = As[kk + r + 4][m + 8];
            }
            #pragma unroll
            for (int ni = 0; ni < NI; ni++) {
                int n = wn + ni * 8 + q;
                bf[ni][0] = Bs[kk + r][n];
                bf[ni][1] = Bs[kk + r + 4][n];
            }
            #pragma unroll
            for (int mi = 0; mi < MI; mi++)
                #pragma unroll
                for (int ni = 0; ni < NI; ni++)
                    mma8(acc[mi][ni], af[mi], bf[ni]);
        }
        __syncthreads();
    }

    // ---- epilogue
    {
        int q = lane >> 2, r2 = (lane & 3) * 2;
        #pragma unroll
        for (int mi = 0; mi < MI; mi++) {
            int row = row0 + wm + mi * 16 + q;
            #pragma unroll
            for (int ni = 0; ni < NI; ni++) {
                int col = col0 + wn + ni * 8 + r2;
                float2 v0 = make_float2(acc[mi][ni][0], acc[mi][ni][1]);
                float2 v1 = make_float2(acc[mi][ni][2], acc[mi][ni][3]);
                if (R) {
                    float2 r0 = *(const float2*)&R[(size_t)row * ldc + col];
                    float2 r1 = *(const float2*)&R[(size_t)(row + 8) * ldc + col];
                    v0.x += r0.x; v0.y += r0.y;
                    v1.x += r1.x; v1.y += r1.y;
                }
                *(float2*)&C[(size_t)row * ldc + col]       = v0;
                *(float2*)&C[(size_t)(row + 8) * ldc + col] = v1;
            }
        }
    }
}

// ---------------------------------------------------------------------------
// Reductions
// ---------------------------------------------------------------------------
__device__ __forceinline__ float block_reduce_sum(float val, float* sdata) {
    int t = threadIdx.x;
    #pragma unroll
    for (int off = 16; off > 0; off >>= 1)
        val += __shfl_down_sync(0xffffffff, val, off);
    if ((t & 31) == 0) sdata[t >> 5] = val;
    __syncthreads();
    if (t < 32) {
        float v = (t < 8) ? sdata[t] : 0.0f;
        #pragma unroll
        for (int off = 4; off > 0; off >>= 1)
            v += __shfl_down_sync(0xffffffff, v, off);
        if (t == 0) sdata[0] = v;
    }
    __syncthreads();
    float r = sdata[0];
    __syncthreads();
    return r;
}

__device__ __forceinline__ float block_reduce_max(float val, float* sdata) {
    int t = threadIdx.x;
    #pragma unroll
    for (int off = 16; off > 0; off >>= 1)
        val = fmaxf(val, __shfl_down_sync(0xffffffff, val, off));
    if ((t & 31) == 0) sdata[t >> 5] = val;
    __syncthreads();
    if (t < 32) {
        float v = (t < 8) ? sdata[t] : -INFINITY;
        #pragma unroll
        for (int off = 4; off > 0; off >>= 1)
            v = fmaxf(v, __shfl_down_sync(0xffffffff, v, off));
        if (t == 0) sdata[0] = v;
    }
    __syncthreads();
    float r = sdata[0];
    __syncthreads();
    return r;
}

// ---------------------------------------------------------------------------
// Softmax over rows of S (in place). Row = 1024 scores; scale 0.125 applied.
// extraFlag: probability doubled for j >= 1008 (duplicated mem keys).
// ---------------------------------------------------------------------------
__global__ __launch_bounds__(256)
void softmax_kernel(float* __restrict__ S, int extraFlag) {
    __shared__ float sdata[32];
    size_t row = blockIdx.x;
    float* r = S + row * 1024;
    int t = threadIdx.x;
    float v[4];
    #pragma unroll
    for (int i = 0; i < 4; i++) v[i] = r[t + 256 * i] * 0.125f;
    float m = fmaxf(fmaxf(v[0], v[1]), fmaxf(v[2], v[3]));
    m = block_reduce_max(m, sdata);
    float p[4];
    float sum = 0.0f;
    #pragma unroll
    for (int i = 0; i < 4; i++) {
        p[i] = expf(v[i] - m);
        if (extraFlag && (t + 256 * i) >= 1008) p[i] *= 2.0f;
        sum += p[i];
    }
    sum = block_reduce_sum(sum, sdata);
    float inv = 1.0f / sum;
    #pragma unroll
    for (int i = 0; i < 4; i++) r[t + 256 * i] = p[i] * inv;
}

// ---------------------------------------------------------------------------
// LayerNorms
// ---------------------------------------------------------------------------
__global__ __launch_bounds__(256)
void ln_kernel(const float* __restrict__ x, const float* __restrict__ g,
               const float* __restrict__ bb, float* __restrict__ out) {
    __shared__ float sdata[32];
    int row = blockIdx.x;
    int t = threadIdx.x;
    const float* xr = x + (size_t)row * D_MODEL;
    float v[4];
    #pragma unroll
    for (int i = 0; i < 4; i++) v[i] = xr[t + 256 * i];
    float s = v[0] + v[1] + v[2] + v[3];
    float mu = block_reduce_sum(s, sdata) * (1.0f / 1024.0f);
    float sq = 0.f;
    #pragma unroll
    for (int i = 0; i < 4; i++) { float d0 = v[i] - mu; sq += d0 * d0; }
    float var = block_reduce_sum(sq, sdata) * (1.0f / 1024.0f);
    float inv = 1.0f / sqrtf(var + 1e-5f);
    float* orow = out + (size_t)row * D_MODEL;
    #pragma unroll
    for (int i = 0; i < 4; i++) {
        int c = t + 256 * i;
        orow[c] = (v[i] - mu) * inv * g[c] + bb[c];
    }
}

// a = LN(proj)*g1+b1 ; y = hids + a ; out = LN(y)*g2+b2
__global__ __launch_bounds__(256)
void ln_ln_kernel(const float* __restrict__ proj,
                  const float* __restrict__ g1, const float* __restrict__ b1,
                  const float* __restrict__ hids,
                  const float* __restrict__ g2, const float* __restrict__ b2,
                  float* __restrict__ out) {
    __shared__ float sdata[32];
    int row = blockIdx.x;
    int t = threadIdx.x;
    const float* xr = proj + (size_t)row * D_MODEL;
    const float* hr = hids + (size_t)row * D_MODEL;
    float v[4], hv[4];
    #pragma unroll
    for (int i = 0; i < 4; i++) { v[i] = xr[t + 256 * i]; hv[i] = hr[t + 256 * i]; }
    float s = v[0] + v[1] + v[2] + v[3];
    float mu = block_reduce_sum(s, sdata) * (1.0f / 1024.0f);
    float sq = 0.f;
    #pragma unroll
    for (int i = 0; i < 4; i++) { float d0 = v[i] - mu; sq += d0 * d0; }
    float var = block_reduce_sum(sq, sdata) * (1.0f / 1024.0f);
    float inv = 1.0f / sqrtf(var + 1e-5f);
    float y[4];
    #pragma unroll
    for (int i = 0; i < 4; i++) {
        int c = t + 256 * i;
        y[i] = hv[i] + (v[i] - mu) * inv * g1[c] + b1[c];
    }
    float s2 = y[0] + y[1] + y[2] + y[3];
    float mu2 = block_reduce_sum(s2, sdata) * (1.0f / 1024.0f);
    float sq2 = 0.f;
    #pragma unroll
    for (int i = 0; i < 4; i++) { float d0 = y[i] - mu2; sq2 += d0 * d0; }
    float var2 = block_reduce_sum(sq2, sdata) * (1.0f / 1024.0f);
    float inv2 = 1.0f / sqrtf(var2 + 1e-5f);
    float* orow = out + (size_t)row * D_MODEL;
    #pragma unroll
    for (int i = 0; i < 4; i++) {
        int c = t + 256 * i;
        orow[c] = (y[i] - mu2) * inv2 * g2[c] + b2[c];
    }
}

// new_mem = hids[:, 1008:1024, :]
__global__ void copy_mem_kernel(const float* __restrict__ hids, float* __restrict__ dst) {
    int idx = blockIdx.x * 1024 + threadIdx.x;   // 0 .. 65535
    int b = idx >> 14;
    int rem = idx & 16383;
    int mrow = rem >> 10;
    int d = rem & 1023;
    dst[idx] = hids[((size_t)(b * SEQ + 1008 + mrow)) * D_MODEL + d];
}

// ---------------------------------------------------------------------------
static float* s_hids0   = nullptr;
static float* s_q       = nullptr;
static float* s_kv      = nullptr;
static float* s_attn    = nullptr;
static float* s_proj    = nullptr;
static float* s_hids    = nullptr;
static float* s_outattn = nullptr;
static float* s_scores  = nullptr;

static void resolve_scratch() {
    if (s_hids0) return;
    cudaGetSymbolAddress((void**)&s_hids0,   g_hids0);
    cudaGetSymbolAddress((void**)&s_q,       g_q);
    cudaGetSymbolAddress((void**)&s_kv,      g_kv);
    cudaGetSymbolAddress((void**)&s_attn,    g_attn);
    cudaGetSymbolAddress((void**)&s_proj,    g_proj);
    cudaGetSymbolAddress((void**)&s_hids,    g_hids);
    cudaGetSymbolAddress((void**)&s_outattn, g_outattn);
    cudaGetSymbolAddress((void**)&s_scores,  g_scores);
}

// helper: full attention block: attn = softmax(Q Kt * scale [dup weights]) V
static void run_attention(const float* x, const float* qw, const float* kvw,
                          float* q, float* kv, float* scores, float* attn,
                          int extraFlag) {
    // q = x @ qw ; kv = x @ kvw
    mma_gemm<128, false><<<dim3(8, 32, 1), 256>>>(
        x, qw, nullptr, q, 1024, 1024, 1024, 1024, 0, 0, 0, 0, 0, 0, 1);
    mma_gemm<128, false><<<dim3(16, 32, 1), 256>>>(
        x, kvw, nullptr, kv, 1024, 1024, 2048, 2048, 0, 0, 0, 0, 0, 0, 1);
    // scores[b,h] = Q[b,:,h,:] @ K[b,:,h,:]^T   (K=64, B n-major)
    mma_gemm<128, true><<<dim3(8, 8, 64), 256>>>(
        q, kv, nullptr, scores, 64, 1024, 2048, 1024,
        (long)SEQ * 1024, 64, (long)SEQ * 2048, 64,
        (long)NHEAD * SEQ * SEQ, (long)SEQ * SEQ, NHEAD);
    softmax_kernel<<<BATCH * NHEAD * SEQ, 256>>>(scores, extraFlag);
    // attn[b,:,h,:] = P[b,h] @ V[b,:,h,:]  (N=64, B row-major)
    mma_gemm<64, false><<<dim3(1, 8, 64), 256>>>(
        scores, kv + 1024, nullptr, attn, 1024, 1024, 2048, 1024,
        (long)NHEAD * SEQ * SEQ, (long)SEQ * SEQ, (long)SEQ * 2048, 64,
        (long)SEQ * 1024, 64, NHEAD);
}

extern "C" void kernel_launch(void* const* d_in, const int* in_sizes, int n_in,
                              void* d_out, int out_size) {
    const int*   data  = (const int*)d_in[0];
    // d_in[1] (mem) dead
    const float* emb   = (const float*)d_in[2];
    const float* a_qw  = (const float*)d_in[3];
    const float* a_kvw = (const float*)d_in[4];
    const float* a_ow  = (const float*)d_in[5];
    const float* a_g   = (const float*)d_in[6];
    const float* a_b   = (const float*)d_in[7];
    // d_in[8..15] dead
    const float* o_qw  = (const float*)d_in[16];
    const float* o_kvw = (const float*)d_in[17];
    const float* o_ow  = (const float*)d_in[18];
    const float* o_g   = (const float*)d_in[19];
    const float* o_b   = (const float*)d_in[20];
    const float* ff2_w = (const float*)d_in[21];
    const float* ln1_g = (const float*)d_in[22];
    const float* ln1_b = (const float*)d_in[23];
    const float* ln2_g = (const float*)d_in[24];
    const float* ln2_b = (const float*)d_in[25];
    float* out = (float*)d_out;

    resolve_scratch();
    float *hids0 = s_hids0, *q = s_q, *kv = s_kv, *attn = s_attn;
    float *proj = s_proj, *hids = s_hids, *outattn = s_outattn, *scores = s_scores;

    // hids0 = emb[data]*sqrt(D) + pos
    embed_kernel<<<OUT_MAIN / 256, 256>>>(data, emb, hids0);

    // --- self attention (layer) ---
    run_attention(hids0, a_qw, a_kvw, q, kv, scores, attn, 0);
    mma_gemm<128, false><<<dim3(8, 32, 1), 256>>>(
        attn, a_ow, hids0, proj, 1024, 1024, 1024, 1024, 0, 0, 0, 0, 0, 0, 1);
    ln_kernel<<<MROWS, 256>>>(proj, a_g, a_b, hids);

    // new_mem = hids[:,1008:1024,:]
    copy_mem_kernel<<<64, 1024>>>(hids, out + OUT_MAIN);

    // --- OutputAttn (keys >=1008 double-weighted) ---
    run_attention(hids, o_qw, o_kvw, q, kv, scores, attn, 1);
    mma_gemm<128, false><<<dim3(8, 32, 1), 256>>>(
        attn, o_ow, hids, proj, 1024, 1024, 1024, 1024, 0, 0, 0, 0, 0, 0, 1);
    ln_ln_kernel<<<MROWS, 256>>>(proj, o_g, o_b, hids, ln1_g, ln1_b, outattn);

    // output = LN(out_attn @ ff2_w + out_attn, ln2)
    mma_gemm<128, false><<<dim3(8, 32, 1), 256>>>(
        outattn, ff2_w, outattn, proj, 1024, 1024, 1024, 1024, 0, 0, 0, 0, 0, 0, 1);
    ln_kernel<<<MROWS, 256>>>(proj, ln2_g, ln2_b, out);
}

// round 4
// speedup vs baseline: 4.5064x; 1.6530x over previous
#include <cuda_runtime.h>
#include <math.h>

// ---------------------------------------------------------------------------
// MemTransformerLMEncoder — tf32 mma.sync + cp.async + ldmatrix version
// Dead code: UpdateAttn branch + `mem` input unused. new_mem = hids[:,1008:1024].
// OutputAttn = 1024-key softmax with keys >=1008 double-weighted.
// All GEMMs in canonical form C = A @ B^T (both operands k-contiguous):
// weights pre-transposed once per launch, V transposed after kv-proj.
// ---------------------------------------------------------------------------

#define D_MODEL 1024
#define SEQ     1024
#define BATCH   4
#define NHEAD   16
#define DHEAD   64
#define MROWS   (BATCH*SEQ)            // 4096
#define OUT_MAIN (BATCH*SEQ*D_MODEL)   // 4194304

// Scratch (device globals — no allocation allowed)
__device__ float g_hids0[MROWS*D_MODEL];
__device__ float g_qkv[MROWS*3*D_MODEL];        // [4096][3072]: q|k|v
__device__ float g_vt[64*DHEAD*SEQ];            // [b*16+h][64][1024]
__device__ float g_attn[MROWS*D_MODEL];
__device__ float g_proj[MROWS*D_MODEL];
__device__ float g_hids[MROWS*D_MODEL];
__device__ float g_outattn[MROWS*D_MODEL];
__device__ float g_scores[67108864];            // [b][h][1024][1024]
__device__ float g_wTa[3*D_MODEL*D_MODEL];      // a_qw^T | a_kvw^T  [3072][1024]
__device__ float g_wTo[3*D_MODEL*D_MODEL];      // o_qw^T | o_kvw^T
__device__ float g_wTaow[D_MODEL*D_MODEL];
__device__ float g_wToow[D_MODEL*D_MODEL];
__device__ float g_wTff2[D_MODEL*D_MODEL];

// ---------------------------------------------------------------------------
// Embedding * sqrt(D) + sinusoidal positional encoding
// ---------------------------------------------------------------------------
__global__ void embed_kernel(const int* __restrict__ data,
                             const float* __restrict__ emb,
                             float* __restrict__ out) {
    int idx = blockIdx.x * 256 + threadIdx.x;
    int d  = idx & (D_MODEL - 1);
    int bs = idx >> 10;
    int s  = bs & (SEQ - 1);
    int tok = data[bs];
    float freq  = powf(10000.0f, -(float)(d & ~1) * (1.0f / 1024.0f));
    float angle = (float)s * freq;
    float pv = (d & 1) ? cosf(angle) : sinf(angle);
    out[idx] = emb[(size_t)tok * D_MODEL + d] * 32.0f + pv;
}

// ---------------------------------------------------------------------------
// Transposes: dst[n*K + k] = src[k*N + n]
// ---------------------------------------------------------------------------
__global__ void transpose_kernel(const float* __restrict__ src, float* __restrict__ dst,
                                 int K, int N) {
    __shared__ float tile[32][33];
    int kb = blockIdx.y * 32, nb = blockIdx.x * 32;
    int tx = threadIdx.x, ty = threadIdx.y;   // 32 x 8
    #pragma unroll
    for (int i = 0; i < 32; i += 8)
        tile[ty + i][tx] = src[(size_t)(kb + ty + i) * N + nb + tx];
    __syncthreads();
    #pragma unroll
    for (int i = 0; i < 32; i += 8)
        dst[(size_t)(nb + ty + i) * K + kb + tx] = tile[tx][ty + i];
}

// vt[(b*16+h)*64*1024 + d*1024 + t] = qkv[(b*1024+t)*3072 + 2048 + h*64 + d]
__global__ void vtrans_kernel(const float* __restrict__ qkv, float* __restrict__ vt) {
    __shared__ float tile[32][33];
    int bh = blockIdx.z;
    int b = bh >> 4, h = bh & 15;
    int tb = blockIdx.x * 32;   // token tile
    int db = blockIdx.y * 32;   // dim tile
    int tx = threadIdx.x, ty = threadIdx.y;
    const float* src = qkv + ((size_t)b * SEQ) * 3072 + 2048 + h * 64;
    #pragma unroll
    for (int i = 0; i < 32; i += 8)
        tile[ty + i][tx] = src[(size_t)(tb + ty + i) * 3072 + db + tx];
    __syncthreads();
    float* dst = vt + ((size_t)bh * 64) * SEQ;
    #pragma unroll
    for (int i = 0; i < 32; i += 8)
        dst[(size_t)(db + ty + i) * SEQ + tb + tx] = tile[tx][ty + i];
}

// ---------------------------------------------------------------------------
// mma / ldmatrix / cp.async primitives
// ---------------------------------------------------------------------------
__device__ __forceinline__ void mma8(float* c, const unsigned* a, const unsigned* b) {
    asm volatile(
        "mma.sync.aligned.m16n8k8.row.col.f32.tf32.tf32.f32 "
        "{%0,%1,%2,%3}, {%4,%5,%6,%7}, {%8,%9}, {%0,%1,%2,%3};"
        : "+f"(c[0]), "+f"(c[1]), "+f"(c[2]), "+f"(c[3])
        : "r"(a[0]), "r"(a[1]), "r"(a[2]), "r"(a[3]), "r"(b[0]), "r"(b[1]));
}

__device__ __forceinline__ void ldsm4(unsigned* r, unsigned addr) {
    asm volatile("ldmatrix.sync.aligned.m8n8.x4.shared.b16 {%0,%1,%2,%3}, [%4];"
        : "=r"(r[0]), "=r"(r[1]), "=r"(r[2]), "=r"(r[3]) : "r"(addr));
}

__device__ __forceinline__ void cp16(unsigned dst, const float* src) {
    asm volatile("cp.async.ca.shared.global [%0], [%1], 16;" :: "r"(dst), "l"(src));
}

// ---------------------------------------------------------------------------
// Pipelined tf32 GEMM: C[M,N] = A[M,K] @ B[N,K]^T (+resid)
// A row-major k-contig (lda), B n-major k-contig (ldb). Raw fp32 in smem,
// HW truncation to tf32. BM=128, BK=32, 256 thr (8 warps 4m x 2n), 2-stage
// cp.async pipeline, ldmatrix fragment loads.
// Batch z -> (zb, zh) = (z/H2, z%H2).
// ---------------------------------------------------------------------------
template<int BN>
__global__ __launch_bounds__(256, 2)
void mma_gemm2(const float* __restrict__ Ag, const float* __restrict__ Bg,
               const float* __restrict__ resid, float* __restrict__ Cg,
               int K, int lda, int ldb, int ldc,
               long sA1, long sA2, long sB1, long sB2, long sC1, long sC2, int H2) {
    constexpr int BM = 128, BK = 32, LDSW = 36;     // row stride 36 words = 9x16B units
    constexpr int WN = BN / 2, NI = WN / 8, MI = 2;
    constexpr int ASZ = BM * LDSW, BSZ = BN * LDSW; // words per buffer

    extern __shared__ __align__(16) float sm[];

    const int z = blockIdx.z;
    const int zb = z / H2, zh = z % H2;
    const float* A = Ag + (size_t)zb * sA1 + (size_t)zh * sA2;
    const float* B = Bg + (size_t)zb * sB1 + (size_t)zh * sB2;
    float*       C = Cg + (size_t)zb * sC1 + (size_t)zh * sC2;

    const int tid = threadIdx.x, lane = tid & 31, warp = tid >> 5;
    const int row0 = blockIdx.y * BM, col0 = blockIdx.x * BN;
    const int wm = (warp & 3) * 32, wn = (warp >> 2) * WN;

    const unsigned smBase = (unsigned)__cvta_generic_to_shared(sm);
    // ldmatrix per-lane row/col offsets (in words)
    const int aoff = ((lane & 7) + ((lane >> 3) & 1) * 8) * LDSW + ((lane >> 4) & 1) * 4;
    const int boff = ((lane & 7) + ((lane >> 4) & 1) * 8) * LDSW + ((lane >> 3) & 1) * 4;

    float acc[MI][NI][4];
    #pragma unroll
    for (int mi = 0; mi < MI; mi++)
        #pragma unroll
        for (int ni = 0; ni < NI; ni++)
            #pragma unroll
            for (int c = 0; c < 4; c++) acc[mi][ni][c] = 0.0f;

    const int T = K / BK;

    // ---- tile loader (cp.async, 16B chunks) ----
    auto loadTile = [&](int t) {
        int buf = t & 1;
        unsigned aB = smBase + (unsigned)(buf * ASZ) * 4u;
        unsigned bB = smBase + (unsigned)(2 * ASZ + buf * BSZ) * 4u;
        const float* Asrc = A + (size_t)row0 * lda + t * BK;
        #pragma unroll
        for (int s = 0; s < 4; s++) {
            int c = tid + 256 * s;
            int m = c >> 3, kc = (c & 7) * 4;
            cp16(aB + (unsigned)(m * LDSW + kc) * 4u, Asrc + (size_t)m * lda + kc);
        }
        const float* Bsrc = B + (size_t)col0 * ldb + t * BK;
        #pragma unroll
        for (int s = 0; s < BN / 32; s++) {
            int c = tid + 256 * s;
            int n = c >> 3, kc = (c & 7) * 4;
            cp16(bB + (unsigned)(n * LDSW + kc) * 4u, Bsrc + (size_t)n * ldb + kc);
        }
    };

    loadTile(0);
    asm volatile("cp.async.commit_group;" ::: "memory");

    for (int t = 0; t < T; t++) {
        if (t + 1 < T) {
            loadTile(t + 1);
            asm volatile("cp.async.commit_group;" ::: "memory");
            asm volatile("cp.async.wait_group 1;" ::: "memory");
        } else {
            asm volatile("cp.async.wait_group 0;" ::: "memory");
        }
        __syncthreads();

        int buf = t & 1;
        unsigned aB = smBase + (unsigned)(buf * ASZ) * 4u;
        unsigned bB = smBase + (unsigned)(2 * ASZ + buf * BSZ) * 4u;
        #pragma unroll
        for (int kk = 0; kk < BK; kk += 8) {
            unsigned af[MI][4];
            #pragma unroll
            for (int mi = 0; mi < MI; mi++)
                ldsm4(af[mi], aB + (unsigned)((wm + mi * 16) * LDSW + kk + aoff) * 4u);
            #pragma unroll
            for (int nb = 0; nb < NI / 2; nb++) {
                unsigned bf[4];
                ldsm4(bf, bB + (unsigned)((wn + nb * 16) * LDSW + kk + boff) * 4u);
                #pragma unroll
                for (int mi = 0; mi < MI; mi++) {
                    mma8(acc[mi][2 * nb],     af[mi], bf);
                    mma8(acc[mi][2 * nb + 1], af[mi], bf + 2);
                }
            }
        }
        __syncthreads();
    }

    // ---- epilogue ----
    {
        int q = lane >> 2, r2 = (lane & 3) * 2;
        #pragma unroll
        for (int mi = 0; mi < MI; mi++) {
            int row = row0 + wm + mi * 16 + q;
            #pragma unroll
            for (int ni = 0; ni < NI; ni++) {
                int col = col0 + wn + ni * 8 + r2;
                float2 v0 = make_float2(acc[mi][ni][0], acc[mi][ni][1]);
                float2 v1 = make_float2(acc[mi][ni][2], acc[mi][ni][3]);
                if (resid) {
                    float2 r0 = *(const float2*)&resid[(size_t)row * ldc + col];
                    float2 r1 = *(const float2*)&resid[(size_t)(row + 8) * ldc + col];
                    v0.x += r0.x; v0.y += r0.y;
                    v1.x += r1.x; v1.y += r1.y;
                }
                *(float2*)&C[(size_t)row * ldc + col]       = v0;
                *(float2*)&C[(size_t)(row + 8) * ldc + col] = v1;
            }
        }
    }
}

// smem sizes (bytes)
#define SMEM128 ((2*128*36 + 2*128*36) * 4)   // 73728
#define SMEM64  ((2*128*36 + 2*64*36) * 4)    // 55296

// ---------------------------------------------------------------------------
// Reductions
// ---------------------------------------------------------------------------
__device__ __forceinline__ float block_reduce_sum(float val, float* sdata) {
    int t = threadIdx.x;
    #pragma unroll
    for (int off = 16; off > 0; off >>= 1)
        val += __shfl_down_sync(0xffffffff, val, off);
    if ((t & 31) == 0) sdata[t >> 5] = val;
    __syncthreads();
    if (t < 32) {
        float v = (t < 8) ? sdata[t] : 0.0f;
        #pragma unroll
        for (int off = 4; off > 0; off >>= 1)
            v += __shfl_down_sync(0xffffffff, v, off);
        if (t == 0) sdata[0] = v;
    }
    __syncthreads();
    float r = sdata[0];
    __syncthreads();
    return r;
}

__device__ __forceinline__ float block_reduce_max(float val, float* sdata) {
    int t = threadIdx.x;
    #pragma unroll
    for (int off = 16; off > 0; off >>= 1)
        val = fmaxf(val, __shfl_down_sync(0xffffffff, val, off));
    if ((t & 31) == 0) sdata[t >> 5] = val;
    __syncthreads();
    if (t < 32) {
        float v = (t < 8) ? sdata[t] : -INFINITY;
        #pragma unroll
        for (int off = 4; off > 0; off >>= 1)
            v = fmaxf(v, __shfl_down_sync(0xffffffff, v, off));
        if (t == 0) sdata[0] = v;
    }
    __syncthreads();
    float r = sdata[0];
    __syncthreads();
    return r;
}

// ---------------------------------------------------------------------------
// Softmax over rows of S (in place). Scale 0.125; extraFlag doubles j>=1008.
// ---------------------------------------------------------------------------
__global__ __launch_bounds__(256)
void softmax_kernel(float* __restrict__ S, int extraFlag) {
    __shared__ float sdata[32];
    size_t row = blockIdx.x;
    float* r = S + row * 1024;
    int t = threadIdx.x;
    float v[4];
    #pragma unroll
    for (int i = 0; i < 4; i++) v[i] = r[t + 256 * i] * 0.125f;
    float m = fmaxf(fmaxf(v[0], v[1]), fmaxf(v[2], v[3]));
    m = block_reduce_max(m, sdata);
    float p[4];
    float sum = 0.0f;
    #pragma unroll
    for (int i = 0; i < 4; i++) {
        p[i] = expf(v[i] - m);
        if (extraFlag && (t + 256 * i) >= 1008) p[i] *= 2.0f;
        sum += p[i];
    }
    sum = block_reduce_sum(sum, sdata);
    float inv = 1.0f / sum;
    #pragma unroll
    for (int i = 0; i < 4; i++) r[t + 256 * i] = p[i] * inv;
}

// ---------------------------------------------------------------------------
// LayerNorms
// ---------------------------------------------------------------------------
__global__ __launch_bounds__(256)
void ln_kernel(const float* __restrict__ x, const float* __restrict__ g,
               const float* __restrict__ bb, float* __restrict__ out) {
    __shared__ float sdata[32];
    int row = blockIdx.x;
    int t = threadIdx.x;
    const float* xr = x + (size_t)row * D_MODEL;
    float v[4];
    #pragma unroll
    for (int i = 0; i < 4; i++) v[i] = xr[t + 256 * i];
    float s = v[0] + v[1] + v[2] + v[3];
    float mu = block_reduce_sum(s, sdata) * (1.0f / 1024.0f);
    float sq = 0.f;
    #pragma unroll
    for (int i = 0; i < 4; i++) { float d0 = v[i] - mu; sq += d0 * d0; }
    float var = block_reduce_sum(sq, sdata) * (1.0f / 1024.0f);
    float inv = 1.0f / sqrtf(var + 1e-5f);
    float* orow = out + (size_t)row * D_MODEL;
    #pragma unroll
    for (int i = 0; i < 4; i++) {
        int c = t + 256 * i;
        orow[c] = (v[i] - mu) * inv * g[c] + bb[c];
    }
}

// a = LN(proj)*g1+b1 ; y = hids + a ; out = LN(y)*g2+b2
__global__ __launch_bounds__(256)
void ln_ln_kernel(const float* __restrict__ proj,
                  const float* __restrict__ g1, const float* __restrict__ b1,
                  const float* __restrict__ hids,
                  const float* __restrict__ g2, const float* __restrict__ b2,
                  float* __restrict__ out) {
    __shared__ float sdata[32];
    int row = blockIdx.x;
    int t = threadIdx.x;
    const float* xr = proj + (size_t)row * D_MODEL;
    const float* hr = hids + (size_t)row * D_MODEL;
    float v[4], hv[4];
    #pragma unroll
    for (int i = 0; i < 4; i++) { v[i] = xr[t + 256 * i]; hv[i] = hr[t + 256 * i]; }
    float s = v[0] + v[1] + v[2] + v[3];
    float mu = block_reduce_sum(s, sdata) * (1.0f / 1024.0f);
    float sq = 0.f;
    #pragma unroll
    for (int i = 0; i < 4; i++) { float d0 = v[i] - mu; sq += d0 * d0; }
    float var = block_reduce_sum(sq, sdata) * (1.0f / 1024.0f);
    float inv = 1.0f / sqrtf(var + 1e-5f);
    float y[4];
    #pragma unroll
    for (int i = 0; i < 4; i++) {
        int c = t + 256 * i;
        y[i] = hv[i] + (v[i] - mu) * inv * g1[c] + b1[c];
    }
    float s2 = y[0] + y[1] + y[2] + y[3];
    float mu2 = block_reduce_sum(s2, sdata) * (1.0f / 1024.0f);
    float sq2 = 0.f;
    #pragma unroll
    for (int i = 0; i < 4; i++) { float d0 = y[i] - mu2; sq2 += d0 * d0; }
    float var2 = block_reduce_sum(sq2, sdata) * (1.0f / 1024.0f);
    float inv2 = 1.0f / sqrtf(var2 + 1e-5f);
    float* orow = out + (size_t)row * D_MODEL;
    #pragma unroll
    for (int i = 0; i < 4; i++) {
        int c = t + 256 * i;
        orow[c] = (y[i] - mu2) * inv2 * g2[c] + b2[c];
    }
}

// new_mem = hids[:, 1008:1024, :]
__global__ void copy_mem_kernel(const float* __restrict__ hids, float* __restrict__ dst) {
    int idx = blockIdx.x * 1024 + threadIdx.x;
    int b = idx >> 14;
    int rem = idx & 16383;
    int mrow = rem >> 10;
    int d = rem & 1023;
    dst[idx] = hids[((size_t)(b * SEQ + 1008 + mrow)) * D_MODEL + d];
}

// ---------------------------------------------------------------------------
static float* s_hids0   = nullptr;
static float* s_qkv     = nullptr;
static float* s_vt      = nullptr;
static float* s_attn    = nullptr;
static float* s_proj    = nullptr;
static float* s_hids    = nullptr;
static float* s_outattn = nullptr;
static float* s_scores  = nullptr;
static float* s_wTa     = nullptr;
static float* s_wTo     = nullptr;
static float* s_wTaow   = nullptr;
static float* s_wToow   = nullptr;
static float* s_wTff2   = nullptr;

static void resolve_scratch() {
    if (s_hids0) return;
    cudaGetSymbolAddress((void**)&s_hids0,   g_hids0);
    cudaGetSymbolAddress((void**)&s_qkv,     g_qkv);
    cudaGetSymbolAddress((void**)&s_vt,      g_vt);
    cudaGetSymbolAddress((void**)&s_attn,    g_attn);
    cudaGetSymbolAddress((void**)&s_proj,    g_proj);
    cudaGetSymbolAddress((void**)&s_hids,    g_hids);
    cudaGetSymbolAddress((void**)&s_outattn, g_outattn);
    cudaGetSymbolAddress((void**)&s_scores,  g_scores);
    cudaGetSymbolAddress((void**)&s_wTa,     g_wTa);
    cudaGetSymbolAddress((void**)&s_wTo,     g_wTo);
    cudaGetSymbolAddress((void**)&s_wTaow,   g_wTaow);
    cudaGetSymbolAddress((void**)&s_wToow,   g_wToow);
    cudaGetSymbolAddress((void**)&s_wTff2,   g_wTff2);
    cudaFuncSetAttribute(mma_gemm2<128>, cudaFuncAttributeMaxDynamicSharedMemorySize, SMEM128);
    cudaFuncSetAttribute(mma_gemm2<64>,  cudaFuncAttributeMaxDynamicSharedMemorySize, SMEM64);
}

// attention: qkv = x@[qw|kvw], scores = QK^T, softmax, attn = PV
static void run_attention(const float* x, const float* wT, int extraFlag) {
    // fused q|k|v projection: [4096,3072] = x @ wT^T
    mma_gemm2<128><<<dim3(24, 32, 1), 256, SMEM128>>>(
        x, wT, nullptr, s_qkv, 1024, 1024, 1024, 3072, 0, 0, 0, 0, 0, 0, 1);
    // vt = V^T per (b,h)
    vtrans_kernel<<<dim3(32, 2, 64), dim3(32, 8)>>>(s_qkv, s_vt);
    // scores[b,h] = Q K^T  (K=64)
    mma_gemm2<128><<<dim3(8, 8, 64), 256, SMEM128>>>(
        s_qkv, s_qkv + 1024, nullptr, s_scores, 64, 3072, 3072, 1024,
        (long)SEQ * 3072, 64, (long)SEQ * 3072, 64,
        (long)NHEAD * SEQ * SEQ, (long)SEQ * SEQ, NHEAD);
    softmax_kernel<<<BATCH * NHEAD * SEQ, 256>>>(s_scores, extraFlag);
    // attn[b,:,h,:] = P @ V  via  P @ (V^T)^T
    mma_gemm2<64><<<dim3(1, 8, 64), 256, SMEM64>>>(
        s_scores, s_vt, nullptr, s_attn, 1024, 1024, 1024, 1024,
        (long)NHEAD * SEQ * SEQ, (long)SEQ * SEQ,
        (long)NHEAD * DHEAD * SEQ, (long)DHEAD * SEQ,
        (long)SEQ * 1024, 64, NHEAD);
}

extern "C" void kernel_launch(void* const* d_in, const int* in_sizes, int n_in,
                              void* d_out, int out_size) {
    const int*   data  = (const int*)d_in[0];
    // d_in[1] (mem) dead
    const float* emb   = (const float*)d_in[2];
    const float* a_qw  = (const float*)d_in[3];
    const float* a_kvw = (const float*)d_in[4];
    const float* a_ow  = (const float*)d_in[5];
    const float* a_g   = (const float*)d_in[6];
    const float* a_b   = (const float*)d_in[7];
    // d_in[8..15] dead
    const float* o_qw  = (const float*)d_in[16];
    const float* o_kvw = (const float*)d_in[17];
    const float* o_ow  = (const float*)d_in[18];
    const float* o_g   = (const float*)d_in[19];
    const float* o_b   = (const float*)d_in[20];
    const float* ff2_w = (const float*)d_in[21];
    const float* ln1_g = (const float*)d_in[22];
    const float* ln1_b = (const float*)d_in[23];
    const float* ln2_g = (const float*)d_in[24];
    const float* ln2_b = (const float*)d_in[25];
    float* out = (float*)d_out;

    resolve_scratch();

    dim3 tb(32, 8);
    // weight transposes (k-contiguous canonical form)
    transpose_kernel<<<dim3(32, 32), tb>>>(a_qw,  s_wTa, 1024, 1024);
    transpose_kernel<<<dim3(64, 32), tb>>>(a_kvw, s_wTa + 1024 * 1024, 1024, 2048);
    transpose_kernel<<<dim3(32, 32), tb>>>(o_qw,  s_wTo, 1024, 1024);
    transpose_kernel<<<dim3(64, 32), tb>>>(o_kvw, s_wTo + 1024 * 1024, 1024, 2048);
    transpose_kernel<<<dim3(32, 32), tb>>>(a_ow,  s_wTaow, 1024, 1024);
    transpose_kernel<<<dim3(32, 32), tb>>>(o_ow,  s_wToow, 1024, 1024);
    transpose_kernel<<<dim3(32, 32), tb>>>(ff2_w, s_wTff2, 1024, 1024);

    // hids0 = emb[data]*sqrt(D) + pos
    embed_kernel<<<OUT_MAIN / 256, 256>>>(data, emb, s_hids0);

    // --- self attention (layer) ---
    run_attention(s_hids0, s_wTa, 0);
    mma_gemm2<128><<<dim3(8, 32, 1), 256, SMEM128>>>(
        s_attn, s_wTaow, s_hids0, s_proj, 1024, 1024, 1024, 1024, 0, 0, 0, 0, 0, 0, 1);
    ln_kernel<<<MROWS, 256>>>(s_proj, a_g, a_b, s_hids);

    // new_mem = hids[:,1008:1024,:]
    copy_mem_kernel<<<64, 1024>>>(s_hids, out + OUT_MAIN);

    // --- OutputAttn (keys >=1008 double-weighted) ---
    run_attention(s_hids, s_wTo, 1);
    mma_gemm2<128><<<dim3(8, 32, 1), 256, SMEM128>>>(
        s_attn, s_wToow, s_hids, s_proj, 1024, 1024, 1024, 1024, 0, 0, 0, 0, 0, 0, 1);
    ln_ln_kernel<<<MROWS, 256>>>(s_proj, o_g, o_b, s_hids, ln1_g, ln1_b, s_outattn);

    // output = LN(out_attn @ ff2_w + out_attn, ln2)
    mma_gemm2<128><<<dim3(8, 32, 1), 256, SMEM128>>>(
        s_outattn, s_wTff2, s_outattn, s_proj, 1024, 1024, 1024, 1024, 0, 0, 0, 0, 0, 0, 1);
    ln_kernel<<<MROWS, 256>>>(s_proj, ln2_g, ln2_b, out);
}

// round 7
// speedup vs baseline: 5.3735x; 1.1924x over previous
// Theory (round 7 submission of the round-4 design):
// - Fused tf32 flash attention per (b,h,128-query-tile): S-tile written to the
//   dedicated P smem region, online softmax with key>=1008 doubling (the
//   duplicated mem keys of OutputAttn), O accumulated in registers, K/V
//   double-buffered via cp.async. Removes ~2 GB score traffic, softmax +
//   vtrans launches, and the inefficient K=64 GEMM of round 4.
// - rna-rounded tf32 on weight transposes and qkv-projection outputs to
//   reclaim accuracy lost to HMMA truncation (rel_err 5.6e-4 -> ~3-4e-4).
// Prediction: dur_us 1080 -> ~780-830.
#include <cuda_runtime.h>
#include <math.h>

#define D_MODEL 1024
#define SEQ     1024
#define BATCH   4
#define NHEAD   16
#define DHEAD   64
#define MROWS   (BATCH*SEQ)            // 4096
#define OUT_MAIN (BATCH*SEQ*D_MODEL)   // 4194304

// Scratch (device globals -- no allocation allowed)
__device__ float g_hids0[MROWS*D_MODEL];
__device__ float g_qkv[MROWS*3*D_MODEL];        // [4096][3072]: q|k|v
__device__ float g_attn[MROWS*D_MODEL];
__device__ float g_proj[MROWS*D_MODEL];
__device__ float g_hids[MROWS*D_MODEL];
__device__ float g_outattn[MROWS*D_MODEL];
__device__ float g_wTa[3*D_MODEL*D_MODEL];      // a_qw^T | a_kvw^T  [3072][1024]
__device__ float g_wTo[3*D_MODEL*D_MODEL];      // o_qw^T | o_kvw^T
__device__ float g_wTaow[D_MODEL*D_MODEL];
__device__ float g_wToow[D_MODEL*D_MODEL];
__device__ float g_wTff2[D_MODEL*D_MODEL];

__device__ __forceinline__ unsigned f2tf(float f) {
    unsigned u;
    asm("cvt.rna.tf32.f32 %0, %1;" : "=r"(u) : "f"(f));
    return u;
}
__device__ __forceinline__ float rndtf(float f) { return __uint_as_float(f2tf(f)); }

__device__ __forceinline__ void mma8(float* c, const unsigned* a, const unsigned* b) {
    asm volatile(
        "mma.sync.aligned.m16n8k8.row.col.f32.tf32.tf32.f32 "
        "{%0,%1,%2,%3}, {%4,%5,%6,%7}, {%8,%9}, {%0,%1,%2,%3};"
        : "+f"(c[0]), "+f"(c[1]), "+f"(c[2]), "+f"(c[3])
        : "r"(a[0]), "r"(a[1]), "r"(a[2]), "r"(a[3]), "r"(b[0]), "r"(b[1]));
}
__device__ __forceinline__ void ldsm4(unsigned* r, unsigned addr) {
    asm volatile("ldmatrix.sync.aligned.m8n8.x4.shared.b16 {%0,%1,%2,%3}, [%4];"
        : "=r"(r[0]), "=r"(r[1]), "=r"(r[2]), "=r"(r[3]) : "r"(addr));
}
__device__ __forceinline__ void cp16(unsigned dst, const float* src) {
    asm volatile("cp.async.ca.shared.global [%0], [%1], 16;" :: "r"(dst), "l"(src));
}

// ---------------------------------------------------------------------------
// Embedding * sqrt(D) + sinusoidal positional encoding
// ---------------------------------------------------------------------------
__global__ void embed_kernel(const int* __restrict__ data,
                             const float* __restrict__ emb,
                             float* __restrict__ out) {
    int idx = blockIdx.x * 256 + threadIdx.x;
    int d  = idx & (D_MODEL - 1);
    int bs = idx >> 10;
    int s  = bs & (SEQ - 1);
    int tok = data[bs];
    float freq  = powf(10000.0f, -(float)(d & ~1) * (1.0f / 1024.0f));
    float angle = (float)s * freq;
    float pv = (d & 1) ? cosf(angle) : sinf(angle);
    out[idx] = emb[(size_t)tok * D_MODEL + d] * 32.0f + pv;
}

// ---------------------------------------------------------------------------
// Weight transpose with tf32-rna rounding: dst[n*K+k] = rna(src[k*N+n])
// ---------------------------------------------------------------------------
__global__ void transpose_kernel(const float* __restrict__ src, float* __restrict__ dst,
                                 int K, int N) {
    __shared__ float tile[32][33];
    int kb = blockIdx.y * 32, nb = blockIdx.x * 32;
    int tx = threadIdx.x, ty = threadIdx.y;   // 32 x 8
    #pragma unroll
    for (int i = 0; i < 32; i += 8)
        tile[ty + i][tx] = src[(size_t)(kb + ty + i) * N + nb + tx];
    __syncthreads();
    #pragma unroll
    for (int i = 0; i < 32; i += 8)
        dst[(size_t)(nb + ty + i) * K + kb + tx] = rndtf(tile[tx][ty + i]);
}

// ---------------------------------------------------------------------------
// Pipelined tf32 GEMM: C[M,N] = A[M,K] @ B[N,K]^T (+resid)
// BM=128, BK=32, 256 thr (8 warps 4m x 2n), 2-stage cp.async, ldmatrix.
// ROUND: rna-round outputs to tf32 (used for qkv which only feeds MMAs).
// ---------------------------------------------------------------------------
template<int BN, bool ROUND>
__global__ __launch_bounds__(256, 2)
void mma_gemm2(const float* __restrict__ Ag, const float* __restrict__ Bg,
               const float* __restrict__ resid, float* __restrict__ Cg,
               int K, int lda, int ldb, int ldc) {
    constexpr int BM = 128, BK = 32, LDSW = 36;
    constexpr int WN = BN / 2, NI = WN / 8, MI = 2;
    constexpr int ASZ = BM * LDSW, BSZ = BN * LDSW;

    extern __shared__ __align__(16) float sm[];
    const float* A = Ag;
    const float* B = Bg;
    float*       C = Cg;

    const int tid = threadIdx.x, lane = tid & 31, warp = tid >> 5;
    const int row0 = blockIdx.y * BM, col0 = blockIdx.x * BN;
    const int wm = (warp & 3) * 32, wn = (warp >> 2) * WN;

    const unsigned smBase = (unsigned)__cvta_generic_to_shared(sm);
    const int aoff = ((lane & 7) + ((lane >> 3) & 1) * 8) * LDSW + ((lane >> 4) & 1) * 4;
    const int boff = ((lane & 7) + ((lane >> 4) & 1) * 8) * LDSW + ((lane >> 3) & 1) * 4;

    float acc[MI][NI][4];
    #pragma unroll
    for (int mi = 0; mi < MI; mi++)
        #pragma unroll
        for (int ni = 0; ni < NI; ni++)
            #pragma unroll
            for (int c = 0; c < 4; c++) acc[mi][ni][c] = 0.0f;

    const int T = K / BK;

    auto loadTile = [&](int t) {
        int buf = t & 1;
        unsigned aB = smBase + (unsigned)(buf * ASZ) * 4u;
        unsigned bB = smBase + (unsigned)(2 * ASZ + buf * BSZ) * 4u;
        const float* Asrc = A + (size_t)row0 * lda + t * BK;
        #pragma unroll
        for (int s = 0; s < 4; s++) {
            int c = tid + 256 * s;
            int m = c >> 3, kc = (c & 7) * 4;
            cp16(aB + (unsigned)(m * LDSW + kc) * 4u, Asrc + (size_t)m * lda + kc);
        }
        const float* Bsrc = B + (size_t)col0 * ldb + t * BK;
        #pragma unroll
        for (int s = 0; s < BN / 32; s++) {
            int c = tid + 256 * s;
            int n = c >> 3, kc = (c & 7) * 4;
            cp16(bB + (unsigned)(n * LDSW + kc) * 4u, Bsrc + (size_t)n * ldb + kc);
        }
    };

    loadTile(0);
    asm volatile("cp.async.commit_group;" ::: "memory");

    for (int t = 0; t < T; t++) {
        if (t + 1 < T) {
            loadTile(t + 1);
            asm volatile("cp.async.commit_group;" ::: "memory");
            asm volatile("cp.async.wait_group 1;" ::: "memory");
        } else {
            asm volatile("cp.async.wait_group 0;" ::: "memory");
        }
        __syncthreads();

        int buf = t & 1;
        unsigned aB = smBase + (unsigned)(buf * ASZ) * 4u;
        unsigned bB = smBase + (unsigned)(2 * ASZ + buf * BSZ) * 4u;
        #pragma unroll
        for (int kk = 0; kk < BK; kk += 8) {
            unsigned af[MI][4];
            #pragma unroll
            for (int mi = 0; mi < MI; mi++)
                ldsm4(af[mi], aB + (unsigned)((wm + mi * 16) * LDSW + kk + aoff) * 4u);
            #pragma unroll
            for (int nb = 0; nb < NI / 2; nb++) {
                unsigned bf[4];
                ldsm4(bf, bB + (unsigned)((wn + nb * 16) * LDSW + kk + boff) * 4u);
                #pragma unroll
                for (int mi = 0; mi < MI; mi++) {
                    mma8(acc[mi][2 * nb],     af[mi], bf);
                    mma8(acc[mi][2 * nb + 1], af[mi], bf + 2);
                }
            }
        }
        __syncthreads();
    }

    {
        int q = lane >> 2, r2 = (lane & 3) * 2;
        #pragma unroll
        for (int mi = 0; mi < MI; mi++) {
            int row = row0 + wm + mi * 16 + q;
            #pragma unroll
            for (int ni = 0; ni < NI; ni++) {
                int col = col0 + wn + ni * 8 + r2;
                float2 v0 = make_float2(acc[mi][ni][0], acc[mi][ni][1]);
                float2 v1 = make_float2(acc[mi][ni][2], acc[mi][ni][3]);
                if (resid) {
                    float2 r0 = *(const float2*)&resid[(size_t)row * ldc + col];
                    float2 r1 = *(const float2*)&resid[(size_t)(row + 8) * ldc + col];
                    v0.x += r0.x; v0.y += r0.y;
                    v1.x += r1.x; v1.y += r1.y;
                }
                if (ROUND) {
                    v0.x = rndtf(v0.x); v0.y = rndtf(v0.y);
                    v1.x = rndtf(v1.x); v1.y = rndtf(v1.y);
                }
                *(float2*)&C[(size_t)row * ldc + col]       = v0;
                *(float2*)&C[(size_t)(row + 8) * ldc + col] = v1;
            }
        }
    }
}

#define SMEM128 ((2*128*36 + 2*128*36) * 4)   // 73728

// ---------------------------------------------------------------------------
// Fused flash attention (tf32 mma). grid=(SEQ/128, B*H), 256 threads.
// qkv row layout [3072]: q at h*64, k at 1024+h*64, v at 2048+h*64.
// Online softmax; keys >=1008 doubled when extraFlag. O accum in regs.
// ---------------------------------------------------------------------------
#define QT    128
#define KT    64
#define QSTR  68     // 17x16B -> ldmatrix conflict-free
#define VSTR  72     // stride%32==8 -> scalar b-frag conflict-free
#define QSZ   (QT*QSTR)                // 8704 words
#define KSZ   (KT*QSTR)                // 4352
#define VSZ   (KT*VSTR)                // 4608
#define OFF_K (QSZ)
#define OFF_V (OFF_K + 2*KSZ)
#define OFF_P (OFF_V + 2*VSZ)
#define OFF_M (OFF_P + QSZ)
#define OFF_L (OFF_M + QT)
#define OFF_C (OFF_L + QT)
#define OFF_R1 (OFF_C + QT)            // 2*QT max partials
#define OFF_R2 (OFF_R1 + 2*QT)         // 2*QT sum partials
#define FA_SMEM ((OFF_R2 + 2*QT) * 4)

__global__ __launch_bounds__(256, 1)
void flash_kernel(const float* __restrict__ qkv, float* __restrict__ O, int extraFlag) {
    extern __shared__ __align__(16) float sm[];
    const int tid = threadIdx.x, lane = tid & 31, warp = tid >> 5;
    const int wm = (warp & 3) * 32, wn = (warp >> 2) * 32;
    const int qb = blockIdx.x;
    const int bh = blockIdx.y;            // b*16 + h
    const int b = bh >> 4, h = bh & 15;
    const int qrow0 = qb * QT;

    const unsigned smBase = (unsigned)__cvta_generic_to_shared(sm);
    const unsigned qB = smBase;
    const unsigned pB = smBase + (unsigned)OFF_P * 4u;
    float* m_s = sm + OFF_M;
    float* l_s = sm + OFF_L;
    float* c_s = sm + OFF_C;
    float* r1  = sm + OFF_R1;
    float* r2  = sm + OFF_R2;

    const int aoff = ((lane & 7) + ((lane >> 3) & 1) * 8) * QSTR + ((lane >> 4) & 1) * 4;
    const int boff = ((lane & 7) + ((lane >> 4) & 1) * 8) * QSTR + ((lane >> 3) & 1) * 4;

    const float* base = qkv + (size_t)(b * SEQ) * 3072 + h * 64;

    // load Q tile (128 x 64)
    {
        const float* Qsrc = base + (size_t)qrow0 * 3072;
        #pragma unroll
        for (int s = 0; s < 8; s++) {
            int c = tid + 256 * s;                 // 0..2047
            int m = c >> 4, kc = (c & 15) * 4;
            cp16(qB + (unsigned)(m * QSTR + kc) * 4u, Qsrc + (size_t)m * 3072 + kc);
        }
    }
    auto loadKV = [&](int t) {
        int buf = t & 1;
        unsigned kB = smBase + (unsigned)(OFF_K + buf * KSZ) * 4u;
        unsigned vB = smBase + (unsigned)(OFF_V + buf * VSZ) * 4u;
        const float* Ksrc = base + (size_t)(t * KT) * 3072 + 1024;
        const float* Vsrc = base + (size_t)(t * KT) * 3072 + 2048;
        #pragma unroll
        for (int s = 0; s < 4; s++) {
            int c = tid + 256 * s;                 // 0..1023
            int n = c >> 4, kc = (c & 15) * 4;
            cp16(kB + (unsigned)(n * QSTR + kc) * 4u, Ksrc + (size_t)n * 3072 + kc);
            cp16(vB + (unsigned)(n * VSTR + kc) * 4u, Vsrc + (size_t)n * 3072 + kc);
        }
    };
    loadKV(0);
    asm volatile("cp.async.commit_group;" ::: "memory");

    if (tid < QT) { m_s[tid] = -INFINITY; l_s[tid] = 0.0f; }

    float oacc[2][4][4];
    #pragma unroll
    for (int mi = 0; mi < 2; mi++)
        #pragma unroll
        for (int ni = 0; ni < 4; ni++)
            #pragma unroll
            for (int c = 0; c < 4; c++) oacc[mi][ni][c] = 0.0f;

    const int NT = SEQ / KT;   // 16
    for (int t = 0; t < NT; t++) {
        if (t + 1 < NT) {
            loadKV(t + 1);
            asm volatile("cp.async.commit_group;" ::: "memory");
            asm volatile("cp.async.wait_group 1;" ::: "memory");
        } else {
            asm volatile("cp.async.wait_group 0;" ::: "memory");
        }
        __syncthreads();

        int buf = t & 1;
        unsigned kB = smBase + (unsigned)(OFF_K + buf * KSZ) * 4u;

        // S = Q K^T (128x64, k=64)
        float sacc[2][4][4];
        #pragma unroll
        for (int mi = 0; mi < 2; mi++)
            #pragma unroll
            for (int ni = 0; ni < 4; ni++)
                #pragma unroll
                for (int c = 0; c < 4; c++) sacc[mi][ni][c] = 0.0f;
        #pragma unroll
        for (int kk = 0; kk < 64; kk += 8) {
            unsigned af[2][4];
            #pragma unroll
            for (int mi = 0; mi < 2; mi++)
                ldsm4(af[mi], qB + (unsigned)((wm + mi * 16) * QSTR + kk + aoff) * 4u);
            #pragma unroll
            for (int nb = 0; nb < 2; nb++) {
                unsigned bf[4];
                ldsm4(bf, kB + (unsigned)((wn + nb * 16) * QSTR + kk + boff) * 4u);
                #pragma unroll
                for (int mi = 0; mi < 2; mi++) {
                    mma8(sacc[mi][2 * nb],     af[mi], bf);
                    mma8(sacc[mi][2 * nb + 1], af[mi], bf + 2);
                }
            }
        }
        // write scaled S to the P buffer
        {
            int q = lane >> 2, r2c = (lane & 3) * 2;
            #pragma unroll
            for (int mi = 0; mi < 2; mi++) {
                int row = wm + mi * 16 + q;
                #pragma unroll
                for (int ni = 0; ni < 4; ni++) {
                    int col = wn + ni * 8 + r2c;
                    *(float2*)(sm + OFF_P + (size_t)row * QSTR + col) =
                        make_float2(sacc[mi][ni][0] * 0.125f, sacc[mi][ni][1] * 0.125f);
                    *(float2*)(sm + OFF_P + (size_t)(row + 8) * QSTR + col) =
                        make_float2(sacc[mi][ni][2] * 0.125f, sacc[mi][ni][3] * 0.125f);
                }
            }
        }
        __syncthreads();

        // softmax update (2 threads per row)
        {
            int row = tid & 127, half = tid >> 7;
            float* pr = sm + OFF_P + (size_t)row * QSTR + half * 32;
            float lm = -INFINITY;
            float v[32];
            #pragma unroll
            for (int i = 0; i < 32; i++) { v[i] = pr[i]; lm = fmaxf(lm, v[i]); }
            r1[half * QT + row] = lm;
            __syncthreads();
            float tm = fmaxf(r1[row], r1[QT + row]);
            float newm = fmaxf(m_s[row], tm);
            float sum = 0.0f;
            int gbase = t * KT + half * 32;
            #pragma unroll
            for (int i = 0; i < 32; i++) {
                float p = __expf(v[i] - newm);
                if (extraFlag && (gbase + i) >= 1008) p *= 2.0f;
                sum += p;
                pr[i] = rndtf(p);
            }
            r2[half * QT + row] = sum;
            __syncthreads();
            if (half == 0) {
                float c = __expf(m_s[row] - newm);
                l_s[row] = l_s[row] * c + r2[row] + r2[QT + row];
                m_s[row] = newm;
                c_s[row] = c;
            }
        }
        __syncthreads();

        // rescale O, then O += P V
        {
            int q = lane >> 2;
            #pragma unroll
            for (int mi = 0; mi < 2; mi++) {
                float c0 = c_s[wm + mi * 16 + q];
                float c1 = c_s[wm + mi * 16 + q + 8];
                #pragma unroll
                for (int ni = 0; ni < 4; ni++) {
                    oacc[mi][ni][0] *= c0; oacc[mi][ni][1] *= c0;
                    oacc[mi][ni][2] *= c1; oacc[mi][ni][3] *= c1;
                }
            }
        }
        #pragma unroll
        for (int kk = 0; kk < KT; kk += 8) {
            unsigned af[2][4];
            #pragma unroll
            for (int mi = 0; mi < 2; mi++)
                ldsm4(af[mi], pB + (unsigned)((wm + mi * 16) * QSTR + kk + aoff) * 4u);
            int kr = kk + (lane & 3), nq = (lane >> 2);
            #pragma unroll
            for (int ni = 0; ni < 4; ni++) {
                unsigned bf[2];
                bf[0] = __float_as_uint(sm[OFF_V + (size_t)(buf * VSZ) + (size_t)kr * VSTR + wn + ni * 8 + nq]);
                bf[1] = __float_as_uint(sm[OFF_V + (size_t)(buf * VSZ) + (size_t)(kr + 4) * VSTR + wn + ni * 8 + nq]);
                #pragma unroll
                for (int mi = 0; mi < 2; mi++)
                    mma8(oacc[mi][ni], af[mi], bf);
            }
        }
        __syncthreads();
    }

    // finalize: O /= l, write out
    {
        int q = lane >> 2, r2c = (lane & 3) * 2;
        #pragma unroll
        for (int mi = 0; mi < 2; mi++) {
            int row = wm + mi * 16 + q;
            float i0 = 1.0f / l_s[row];
            float i1 = 1.0f / l_s[row + 8];
            #pragma unroll
            for (int ni = 0; ni < 4; ni++) {
                int col = h * 64 + wn + ni * 8 + r2c;
                size_t g0 = (size_t)(b * SEQ + qrow0 + row) * D_MODEL + col;
                size_t g1 = (size_t)(b * SEQ + qrow0 + row + 8) * D_MODEL + col;
                *(float2*)&O[g0] = make_float2(oacc[mi][ni][0] * i0, oacc[mi][ni][1] * i0);
                *(float2*)&O[g1] = make_float2(oacc[mi][ni][2] * i1, oacc[mi][ni][3] * i1);
            }
        }
    }
}

// ---------------------------------------------------------------------------
// Reductions / LN / copies
// ---------------------------------------------------------------------------
__device__ __forceinline__ float block_reduce_sum(float val, float* sdata) {
    int t = threadIdx.x;
    #pragma unroll
    for (int off = 16; off > 0; off >>= 1)
        val += __shfl_down_sync(0xffffffff, val, off);
    if ((t & 31) == 0) sdata[t >> 5] = val;
    __syncthreads();
    if (t < 32) {
        float v = (t < 8) ? sdata[t] : 0.0f;
        #pragma unroll
        for (int off = 4; off > 0; off >>= 1)
            v += __shfl_down_sync(0xffffffff, v, off);
        if (t == 0) sdata[0] = v;
    }
    __syncthreads();
    float r = sdata[0];
    __syncthreads();
    return r;
}

__global__ __launch_bounds__(256)
void ln_kernel(const float* __restrict__ x, const float* __restrict__ g,
               const float* __restrict__ bb, float* __restrict__ out) {
    __shared__ float sdata[32];
    int row = blockIdx.x;
    int t = threadIdx.x;
    const float* xr = x + (size_t)row * D_MODEL;
    float v[4];
    #pragma unroll
    for (int i = 0; i < 4; i++) v[i] = xr[t + 256 * i];
    float s = v[0] + v[1] + v[2] + v[3];
    float mu = block_reduce_sum(s, sdata) * (1.0f / 1024.0f);
    float sq = 0.f;
    #pragma unroll
    for (int i = 0; i < 4; i++) { float d0 = v[i] - mu; sq += d0 * d0; }
    float var = block_reduce_sum(sq, sdata) * (1.0f / 1024.0f);
    float inv = 1.0f / sqrtf(var + 1e-5f);
    float* orow = out + (size_t)row * D_MODEL;
    #pragma unroll
    for (int i = 0; i < 4; i++) {
        int c = t + 256 * i;
        orow[c] = (v[i] - mu) * inv * g[c] + bb[c];
    }
}

__global__ __launch_bounds__(256)
void ln_ln_kernel(const float* __restrict__ proj,
                  const float* __restrict__ g1, const float* __restrict__ b1,
                  const float* __restrict__ hids,
                  const float* __restrict__ g2, const float* __restrict__ b2,
                  float* __restrict__ out) {
    __shared__ float sdata[32];
    int row = blockIdx.x;
    int t = threadIdx.x;
    const float* xr = proj + (size_t)row * D_MODEL;
    const float* hr = hids + (size_t)row * D_MODEL;
    float v[4], hv[4];
    #pragma unroll
    for (int i = 0; i < 4; i++) { v[i] = xr[t + 256 * i]; hv[i] = hr[t + 256 * i]; }
    float s = v[0] + v[1] + v[2] + v[3];
    float mu = block_reduce_sum(s, sdata) * (1.0f / 1024.0f);
    float sq = 0.f;
    #pragma unroll
    for (int i = 0; i < 4; i++) { float d0 = v[i] - mu; sq += d0 * d0; }
    float var = block_reduce_sum(sq, sdata) * (1.0f / 1024.0f);
    float inv = 1.0f / sqrtf(var + 1e-5f);
    float y[4];
    #pragma unroll
    for (int i = 0; i < 4; i++) {
        int c = t + 256 * i;
        y[i] = hv[i] + (v[i] - mu) * inv * g1[c] + b1[c];
    }
    float s2 = y[0] + y[1] + y[2] + y[3];
    float mu2 = block_reduce_sum(s2, sdata) * (1.0f / 1024.0f);
    float sq2 = 0.f;
    #pragma unroll
    for (int i = 0; i < 4; i++) { float d0 = y[i] - mu2; sq2 += d0 * d0; }
    float var2 = block_reduce_sum(sq2, sdata) * (1.0f / 1024.0f);
    float inv2 = 1.0f / sqrtf(var2 + 1e-5f);
    float* orow = out + (size_t)row * D_MODEL;
    #pragma unroll
    for (int i = 0; i < 4; i++) {
        int c = t + 256 * i;
        orow[c] = (y[i] - mu2) * inv2 * g2[c] + b2[c];
    }
}

__global__ void copy_mem_kernel(const float* __restrict__ hids, float* __restrict__ dst) {
    int idx = blockIdx.x * 1024 + threadIdx.x;
    int b = idx >> 14;
    int rem = idx & 16383;
    int mrow = rem >> 10;
    int d = rem & 1023;
    dst[idx] = hids[((size_t)(b * SEQ + 1008 + mrow)) * D_MODEL + d];
}

// ---------------------------------------------------------------------------
static float* s_hids0   = nullptr;
static float* s_qkv     = nullptr;
static float* s_attn    = nullptr;
static float* s_proj    = nullptr;
static float* s_hids    = nullptr;
static float* s_outattn = nullptr;
static float* s_wTa     = nullptr;
static float* s_wTo     = nullptr;
static float* s_wTaow   = nullptr;
static float* s_wToow   = nullptr;
static float* s_wTff2   = nullptr;

static void resolve_scratch() {
    if (s_hids0) return;
    cudaGetSymbolAddress((void**)&s_hids0,   g_hids0);
    cudaGetSymbolAddress((void**)&s_qkv,     g_qkv);
    cudaGetSymbolAddress((void**)&s_attn,    g_attn);
    cudaGetSymbolAddress((void**)&s_proj,    g_proj);
    cudaGetSymbolAddress((void**)&s_hids,    g_hids);
    cudaGetSymbolAddress((void**)&s_outattn, g_outattn);
    cudaGetSymbolAddress((void**)&s_wTa,     g_wTa);
    cudaGetSymbolAddress((void**)&s_wTo,     g_wTo);
    cudaGetSymbolAddress((void**)&s_wTaow,   g_wTaow);
    cudaGetSymbolAddress((void**)&s_wToow,   g_wToow);
    cudaGetSymbolAddress((void**)&s_wTff2,   g_wTff2);
    cudaFuncSetAttribute(mma_gemm2<128, false>, cudaFuncAttributeMaxDynamicSharedMemorySize, SMEM128);
    cudaFuncSetAttribute(mma_gemm2<128, true>,  cudaFuncAttributeMaxDynamicSharedMemorySize, SMEM128);
    cudaFuncSetAttribute(flash_kernel, cudaFuncAttributeMaxDynamicSharedMemorySize, FA_SMEM);
}

static void run_attention(const float* x, const float* wT, int extraFlag) {
    mma_gemm2<128, true><<<dim3(24, 32), 256, SMEM128>>>(
        x, wT, nullptr, s_qkv, 1024, 1024, 1024, 3072);
    flash_kernel<<<dim3(SEQ / QT, BATCH * NHEAD), 256, FA_SMEM>>>(s_qkv, s_attn, extraFlag);
}

extern "C" void kernel_launch(void* const* d_in, const int* in_sizes, int n_in,
                              void* d_out, int out_size) {
    const int*   data  = (const int*)d_in[0];
    const float* emb   = (const float*)d_in[2];
    const float* a_qw  = (const float*)d_in[3];
    const float* a_kvw = (const float*)d_in[4];
    const float* a_ow  = (const float*)d_in[5];
    const float* a_g   = (const float*)d_in[6];
    const float* a_b   = (const float*)d_in[7];
    const float* o_qw  = (const float*)d_in[16];
    const float* o_kvw = (const float*)d_in[17];
    const float* o_ow  = (const float*)d_in[18];
    const float* o_g   = (const float*)d_in[19];
    const float* o_b   = (const float*)d_in[20];
    const float* ff2_w = (const float*)d_in[21];
    const float* ln1_g = (const float*)d_in[22];
    const float* ln1_b = (const float*)d_in[23];
    const float* ln2_g = (const float*)d_in[24];
    const float* ln2_b = (const float*)d_in[25];
    float* out = (float*)d_out;

    resolve_scratch();

    dim3 tb(32, 8);
    transpose_kernel<<<dim3(32, 32), tb>>>(a_qw,  s_wTa, 1024, 1024);
    transpose_kernel<<<dim3(64, 32), tb>>>(a_kvw, s_wTa + 1024 * 1024, 1024, 2048);
    transpose_kernel<<<dim3(32, 32), tb>>>(o_qw,  s_wTo, 1024, 1024);
    transpose_kernel<<<dim3(64, 32), tb>>>(o_kvw, s_wTo + 1024 * 1024, 1024, 2048);
    transpose_kernel<<<dim3(32, 32), tb>>>(a_ow,  s_wTaow, 1024, 1024);
    transpose_kernel<<<dim3(32, 32), tb>>>(o_ow,  s_wToow, 1024, 1024);
    transpose_kernel<<<dim3(32, 32), tb>>>(ff2_w, s_wTff2, 1024, 1024);

    embed_kernel<<<OUT_MAIN / 256, 256>>>(data, emb, s_hids0);

    // self attention (layer)
    run_attention(s_hids0, s_wTa, 0);
    mma_gemm2<128, false><<<dim3(8, 32), 256, SMEM128>>>(
        s_attn, s_wTaow, s_hids0, s_proj, 1024, 1024, 1024, 1024);
    ln_kernel<<<MROWS, 256>>>(s_proj, a_g, a_b, s_hids);

    copy_mem_kernel<<<64, 1024>>>(s_hids, out + OUT_MAIN);

    // OutputAttn (keys >=1008 double-weighted)
    run_attention(s_hids, s_wTo, 1);
    mma_gemm2<128, false><<<dim3(8, 32), 256, SMEM128>>>(
        s_attn, s_wToow, s_hids, s_proj, 1024, 1024, 1024, 1024);
    ln_ln_kernel<<<MROWS, 256>>>(s_proj, o_g, o_b, s_hids, ln1_g, ln1_b, s_outattn);

    mma_gemm2<128, false><<<dim3(8, 32), 256, SMEM128>>>(
        s_outattn, s_wTff2, s_outattn, s_proj, 1024, 1024, 1024, 1024);
    ln_kernel<<<MROWS, 256>>>(s_proj, ln2_g, ln2_b, out);
}

// round 8
// speedup vs baseline: 7.9963x; 1.4881x over previous
#include <cuda_runtime.h>
#include <cuda_fp16.h>
#include <math.h>

// ---------------------------------------------------------------------------
// MemTransformerLMEncoder - fp16 mma.sync (m16n8k16) version, fp32 accum.
// Dead code: UpdateAttn branch + mem input unused. new_mem = hids[:,1008:1024].
// OutputAttn = 1024-key softmax with keys >=1008 double-weighted.
// fp16 has the same 10-bit mantissa as tf32 -> accuracy comparable, 2x mma
// throughput, half the smem/DRAM traffic. Softmax/LN/residual all fp32.
// ---------------------------------------------------------------------------

#define D_MODEL 1024
#define SEQ     1024
#define BATCH   4
#define NHEAD   16
#define DHEAD   64
#define MROWS   (BATCH*SEQ)            // 4096
#define OUT_MAIN (BATCH*SEQ*D_MODEL)   // 4194304

// fp32 scratch
__device__ float g_hids0[MROWS*D_MODEL];
__device__ float g_proj[MROWS*D_MODEL];
__device__ float g_hids[MROWS*D_MODEL];
__device__ float g_outattn[MROWS*D_MODEL];
// fp16 scratch
__device__ __half g_h0h[MROWS*D_MODEL];
__device__ __half g_qkvh[MROWS*3*D_MODEL];
__device__ __half g_attnh[MROWS*D_MODEL];
__device__ __half g_hidsh[MROWS*D_MODEL];
__device__ __half g_outh[MROWS*D_MODEL];
// fp16 transposed weights
__device__ __half g_wTa[3*D_MODEL*D_MODEL];
__device__ __half g_wTo[3*D_MODEL*D_MODEL];
__device__ __half g_wTaow[D_MODEL*D_MODEL];
__device__ __half g_wToow[D_MODEL*D_MODEL];
__device__ __half g_wTff2[D_MODEL*D_MODEL];

// ---------------------------------------------------------------------------
__device__ __forceinline__ void mma16(float* c, const unsigned* a, unsigned b0, unsigned b1) {
    asm volatile(
        "mma.sync.aligned.m16n8k16.row.col.f32.f16.f16.f32 "
        "{%0,%1,%2,%3}, {%4,%5,%6,%7}, {%8,%9}, {%0,%1,%2,%3};"
        : "+f"(c[0]), "+f"(c[1]), "+f"(c[2]), "+f"(c[3])
        : "r"(a[0]), "r"(a[1]), "r"(a[2]), "r"(a[3]), "r"(b0), "r"(b1));
}
__device__ __forceinline__ void ldsm4(unsigned* r, unsigned addr) {
    asm volatile("ldmatrix.sync.aligned.m8n8.x4.shared.b16 {%0,%1,%2,%3}, [%4];"
        : "=r"(r[0]), "=r"(r[1]), "=r"(r[2]), "=r"(r[3]) : "r"(addr));
}
__device__ __forceinline__ void ldsm4t(unsigned* r, unsigned addr) {
    asm volatile("ldmatrix.sync.aligned.m8n8.x4.trans.shared.b16 {%0,%1,%2,%3}, [%4];"
        : "=r"(r[0]), "=r"(r[1]), "=r"(r[2]), "=r"(r[3]) : "r"(addr));
}
__device__ __forceinline__ void cp16(unsigned dst, const void* src) {
    asm volatile("cp.async.ca.shared.global [%0], [%1], 16;" :: "r"(dst), "l"(src));
}

// per-lane ldmatrix offset (halves) for a 16x16 b16 tile, rows stride STR halves
// lanes 0-7: rows 0-7, 8-15: rows 8-15, 16-23: rows 0-7 col+8, 24-31: rows 8-15 col+8
__device__ __forceinline__ int off16(int lane, int STR) {
    return ((lane & 7) + ((lane >> 3) & 1) * 8) * STR + ((lane >> 4) & 1) * 8;
}
// trans variant for V: lanes 0-7 rows 0-7, 8-15: rows 0-7 col+8, 16-23: rows 8-15, 24-31: rows 8-15 col+8
__device__ __forceinline__ int off16v(int lane, int STR) {
    return ((lane & 7) + ((lane >> 4) & 1) * 8) * STR + ((lane >> 3) & 1) * 8;
}

// ---------------------------------------------------------------------------
// Embedding * sqrt(D) + positional encoding -> fp32 + fp16
// ---------------------------------------------------------------------------
__global__ void embed_kernel(const int* __restrict__ data,
                             const float* __restrict__ emb,
                             float* __restrict__ outf, __half* __restrict__ outh) {
    int idx = blockIdx.x * 256 + threadIdx.x;
    int d  = idx & (D_MODEL - 1);
    int bs = idx >> 10;
    int s  = bs & (SEQ - 1);
    int tok = data[bs];
    float freq  = powf(10000.0f, -(float)(d & ~1) * (1.0f / 1024.0f));
    float angle = (float)s * freq;
    float pv = (d & 1) ? cosf(angle) : sinf(angle);
    float v = emb[(size_t)tok * D_MODEL + d] * 32.0f + pv;
    outf[idx] = v;
    outh[idx] = __float2half(v);
}

// ---------------------------------------------------------------------------
// Fused transpose+fp16 convert: 9 units of 1024x1024, dst[n*1024+k]=src[k*ld+n]
// ---------------------------------------------------------------------------
struct TpArgs {
    const float* src[9];
    __half* dst[9];
    int ld[9];
};
__global__ void transpose_h_kernel(TpArgs a) {
    __shared__ float tile[32][33];
    int u = blockIdx.z;
    const float* src = a.src[u];
    __half* dst = a.dst[u];
    int ld = a.ld[u];
    int kb = blockIdx.y * 32, nb = blockIdx.x * 32;
    int tx = threadIdx.x, ty = threadIdx.y;   // 32 x 8
    #pragma unroll
    for (int i = 0; i < 32; i += 8)
        tile[ty + i][tx] = src[(size_t)(kb + ty + i) * ld + nb + tx];
    __syncthreads();
    #pragma unroll
    for (int i = 0; i < 32; i += 8)
        dst[(size_t)(nb + ty + i) * 1024 + kb + tx] = __float2half(tile[tx][ty + i]);
}

// ---------------------------------------------------------------------------
// fp16 GEMM: C[M,N] = A[M,K] @ B[N,K]^T (+fp32 resid). BM=128 BN=128 BK=32,
// 256 thr (8 warps 4m x 2n), 3-stage cp.async, ldmatrix. OUTH: fp16 C.
// ---------------------------------------------------------------------------
#define GSTR 40                         // halves; 80B = 5x16B (odd) conflict-free
#define GAB  (128*GSTR*2)               // bytes per A (or B) buffer = 10240
#define GSMEM (3*2*GAB)                 // 61440

template<bool OUTH>
__global__ __launch_bounds__(256, 2)
void gemm_h(const __half* __restrict__ A, const __half* __restrict__ B,
            const float* __restrict__ resid, void* __restrict__ Cg,
            int K, int lda, int ldb, int ldc) {
    extern __shared__ __align__(16) char smraw[];
    const int tid = threadIdx.x, lane = tid & 31, warp = tid >> 5;
    const int row0 = blockIdx.y * 128, col0 = blockIdx.x * 128;
    const int wm = (warp & 3) * 32, wn = (warp >> 2) * 64;
    const unsigned smBase = (unsigned)__cvta_generic_to_shared(smraw);
    const int offL = off16(lane, GSTR);

    float acc[2][8][4];
    #pragma unroll
    for (int mi = 0; mi < 2; mi++)
        #pragma unroll
        for (int ni = 0; ni < 8; ni++)
            #pragma unroll
            for (int c = 0; c < 4; c++) acc[mi][ni][c] = 0.0f;

    const int T = K / 32;

    auto loadTile = [&](int t) {
        int buf = t % 3;
        unsigned aB = smBase + (unsigned)(buf * 2 * GAB);
        unsigned bB = aB + GAB;
        const __half* Asrc = A + (size_t)row0 * lda + t * 32;
        const __half* Bsrc = B + (size_t)col0 * ldb + t * 32;
        #pragma unroll
        for (int s = 0; s < 2; s++) {
            int c = tid + 256 * s;          // 0..511
            int m = c >> 2, kc = (c & 3) * 8;
            cp16(aB + (unsigned)(m * GSTR + kc) * 2u, Asrc + (size_t)m * lda + kc);
        }
        #pragma unroll
        for (int s = 0; s < 2; s++) {
            int c = tid + 256 * s;
            int n = c >> 2, kc = (c & 3) * 8;
            cp16(bB + (unsigned)(n * GSTR + kc) * 2u, Bsrc + (size_t)n * ldb + kc);
        }
    };

    loadTile(0);
    asm volatile("cp.async.commit_group;" ::: "memory");
    loadTile(1);
    asm volatile("cp.async.commit_group;" ::: "memory");

    for (int t = 0; t < T; t++) {
        if (t + 2 < T) {
            loadTile(t + 2);
            asm volatile("cp.async.commit_group;" ::: "memory");
            asm volatile("cp.async.wait_group 2;" ::: "memory");
        } else if (t + 1 < T) {
            asm volatile("cp.async.wait_group 1;" ::: "memory");
        } else {
            asm volatile("cp.async.wait_group 0;" ::: "memory");
        }
        __syncthreads();

        int buf = t % 3;
        unsigned aB = smBase + (unsigned)(buf * 2 * GAB);
        unsigned bB = aB + GAB;
        #pragma unroll
        for (int kk = 0; kk < 32; kk += 16) {
            unsigned af[2][4];
            #pragma unroll
            for (int mi = 0; mi < 2; mi++)
                ldsm4(af[mi], aB + (unsigned)((wm + mi * 16) * GSTR + kk + offL) * 2u);
            #pragma unroll
            for (int g = 0; g < 4; g++) {
                unsigned bf[4];
                ldsm4(bf, bB + (unsigned)((wn + g * 16) * GSTR + kk + offL) * 2u);
                #pragma unroll
                for (int mi = 0; mi < 2; mi++) {
                    mma16(acc[mi][2 * g],     af[mi], bf[0], bf[2]);
                    mma16(acc[mi][2 * g + 1], af[mi], bf[1], bf[3]);
                }
            }
        }
        __syncthreads();
    }

    {
        int q = lane >> 2, r2 = (lane & 3) * 2;
        #pragma unroll
        for (int mi = 0; mi < 2; mi++) {
            int row = row0 + wm + mi * 16 + q;
            #pragma unroll
            for (int ni = 0; ni < 8; ni++) {
                int col = col0 + wn + ni * 8 + r2;
                float v0 = acc[mi][ni][0], v1 = acc[mi][ni][1];
                float v2 = acc[mi][ni][2], v3 = acc[mi][ni][3];
                if (resid) {
                    float2 r0 = *(const float2*)&resid[(size_t)row * ldc + col];
                    float2 r1 = *(const float2*)&resid[(size_t)(row + 8) * ldc + col];
                    v0 += r0.x; v1 += r0.y; v2 += r1.x; v3 += r1.y;
                }
                if (OUTH) {
                    __half2* C = (__half2*)Cg;
                    C[((size_t)row * ldc + col) >> 1]       = __floats2half2_rn(v0, v1);
                    C[((size_t)(row + 8) * ldc + col) >> 1] = __floats2half2_rn(v2, v3);
                } else {
                    float* C = (float*)Cg;
                    *(float2*)&C[(size_t)row * ldc + col]       = make_float2(v0, v1);
                    *(float2*)&C[(size_t)(row + 8) * ldc + col] = make_float2(v2, v3);
                }
            }
        }
    }
}

// ---------------------------------------------------------------------------
// Fused fp16 flash attention. grid=(SEQ/128, B*H), 256 thr.
// qkvh row [3072]: q at h*64, k at 1024+h*64, v at 2048+h*64.
// K frag: non-trans ldmatrix ([token][d] = col-major k x n for S = Q K^T).
// V frag: ldmatrix.x4.trans on natural [token][d] layout.
// S fp32 in smem; P fp16 aliased over S region (reads precede writes across
// a barrier). Keys >= 1008 doubled when extraFlag.
// ---------------------------------------------------------------------------
#define FSTR 72                         // halves; 144B = 9x16B odd
#define FQH  0
#define FKH  9216
#define FVH  18432
#define FKVB 4608                       // halves per K (or V) buffer
#define FHBYTES 55296                   // bytes of the halves region
#define SSTR 68                         // floats
#define FS_M 8704
#define FS_L 8832
#define FS_C 8960
#define FS_R1 9088
#define FS_R2 9344
#define FA_SMEM (FHBYTES + 9600*4)      // 93696

__global__ __launch_bounds__(256, 2)
void flash_h(const __half* __restrict__ qkv, __half* __restrict__ O, int extraFlag) {
    extern __shared__ __align__(16) char smraw[];
    float* smf = (float*)(smraw + FHBYTES);
    __half* smP = (__half*)smf;
    const int tid = threadIdx.x, lane = tid & 31, warp = tid >> 5;
    const int wm = (warp & 3) * 32, wn = (warp >> 2) * 32;
    const int qb = blockIdx.x;
    const int bh = blockIdx.y;
    const int b = bh >> 4, h = bh & 15;
    const int qrow0 = qb * 128;

    const unsigned smBase = (unsigned)__cvta_generic_to_shared(smraw);
    const unsigned pB = smBase + FHBYTES;
    float* m_s = smf + FS_M;
    float* l_s = smf + FS_L;
    float* c_s = smf + FS_C;
    float* r1  = smf + FS_R1;
    float* r2  = smf + FS_R2;

    const int offL = off16(lane, FSTR);
    const int offV = off16v(lane, FSTR);

    const __half* base = qkv + (size_t)(b * SEQ) * 3072 + h * 64;

    // load Q tile 128x64 halves
    {
        const __half* Qsrc = base + (size_t)qrow0 * 3072;
        #pragma unroll
        for (int s = 0; s < 4; s++) {
            int c = tid + 256 * s;              // 0..1023
            int m = c >> 3, kc = (c & 7) * 8;
            cp16(smBase + (unsigned)(m * FSTR + kc) * 2u, Qsrc + (size_t)m * 3072 + kc);
        }
    }
    auto loadKV = [&](int t) {
        int buf = t & 1;
        unsigned kB = smBase + (unsigned)(FKH + buf * FKVB) * 2u;
        unsigned vB = smBase + (unsigned)(FVH + buf * FKVB) * 2u;
        const __half* Ksrc = base + (size_t)(t * 64) * 3072 + 1024;
        const __half* Vsrc = base + (size_t)(t * 64) * 3072 + 2048;
        #pragma unroll
        for (int s = 0; s < 2; s++) {
            int c = tid + 256 * s;              // 0..511
            int n = c >> 3, kc = (c & 7) * 8;
            cp16(kB + (unsigned)(n * FSTR + kc) * 2u, Ksrc + (size_t)n * 3072 + kc);
            cp16(vB + (unsigned)(n * FSTR + kc) * 2u, Vsrc + (size_t)n * 3072 + kc);
        }
    };
    loadKV(0);
    asm volatile("cp.async.commit_group;" ::: "memory");

    if (tid < 128) { m_s[tid] = -INFINITY; l_s[tid] = 0.0f; }

    float oacc[2][4][4];
    #pragma unroll
    for (int mi = 0; mi < 2; mi++)
        #pragma unroll
        for (int ni = 0; ni < 4; ni++)
            #pragma unroll
            for (int c = 0; c < 4; c++) oacc[mi][ni][c] = 0.0f;

    for (int t = 0; t < 16; t++) {
        if (t + 1 < 16) {
            loadKV(t + 1);
            asm volatile("cp.async.commit_group;" ::: "memory");
            asm volatile("cp.async.wait_group 1;" ::: "memory");
        } else {
            asm volatile("cp.async.wait_group 0;" ::: "memory");
        }
        __syncthreads();

        int buf = t & 1;
        unsigned kB = smBase + (unsigned)(FKH + buf * FKVB) * 2u;
        unsigned vB = smBase + (unsigned)(FVH + buf * FKVB) * 2u;

        // S = Q K^T (128 x 64, k = 64)
        float sacc[2][4][4];
        #pragma unroll
        for (int mi = 0; mi < 2; mi++)
            #pragma unroll
            for (int ni = 0; ni < 4; ni++)
                #pragma unroll
                for (int c = 0; c < 4; c++) sacc[mi][ni][c] = 0.0f;
        #pragma unroll
        for (int kk = 0; kk < 64; kk += 16) {
            unsigned af[2][4];
            #pragma unroll
            for (int mi = 0; mi < 2; mi++)
                ldsm4(af[mi], smBase + (unsigned)((wm + mi * 16) * FSTR + kk + offL) * 2u);
            #pragma unroll
            for (int g = 0; g < 2; g++) {
                unsigned bf[4];
                ldsm4(bf, kB + (unsigned)((wn + g * 16) * FSTR + kk + offL) * 2u);
                #pragma unroll
                for (int mi = 0; mi < 2; mi++) {
                    mma16(sacc[mi][2 * g],     af[mi], bf[0], bf[2]);
                    mma16(sacc[mi][2 * g + 1], af[mi], bf[1], bf[3]);
                }
            }
        }
        // write scaled S (fp32, stride SSTR)
        {
            int q = lane >> 2, r2c = (lane & 3) * 2;
            #pragma unroll
            for (int mi = 0; mi < 2; mi++) {
                int row = wm + mi * 16 + q;
                #pragma unroll
                for (int ni = 0; ni < 4; ni++) {
                    int col = wn + ni * 8 + r2c;
                    *(float2*)(smf + (size_t)row * SSTR + col) =
                        make_float2(sacc[mi][ni][0] * 0.125f, sacc[mi][ni][1] * 0.125f);
                    *(float2*)(smf + (size_t)(row + 8) * SSTR + col) =
                        make_float2(sacc[mi][ni][2] * 0.125f, sacc[mi][ni][3] * 0.125f);
                }
            }
        }
        __syncthreads();

        // softmax (2 threads per row); P (fp16) aliases S region
        {
            int row = tid & 127, half = tid >> 7;
            const float* sr = smf + (size_t)row * SSTR + half * 32;
            float v[32];
            float lm = -INFINITY;
            #pragma unroll
            for (int i = 0; i < 32; i++) { v[i] = sr[i]; lm = fmaxf(lm, v[i]); }
            r1[half * 128 + row] = lm;
            __syncthreads();   // all S reads complete before P writes
            float tm = fmaxf(r1[row], r1[128 + row]);
            float newm = fmaxf(m_s[row], tm);
            float p[32];
            float sum = 0.0f;
            int gbase = t * 64 + half * 32;
            #pragma unroll
            for (int i = 0; i < 32; i++) {
                p[i] = __expf(v[i] - newm);
                if (extraFlag && (gbase + i) >= 1008) p[i] *= 2.0f;
                sum += p[i];
            }
            __half2* pw = (__half2*)(smP + (size_t)row * FSTR + half * 32);
            #pragma unroll
            for (int i = 0; i < 16; i++)
                pw[i] = __floats2half2_rn(p[2 * i], p[2 * i + 1]);
            r2[half * 128 + row] = sum;
            __syncthreads();
            if (half == 0) {
                float c = __expf(m_s[row] - newm);
                l_s[row] = l_s[row] * c + r2[row] + r2[128 + row];
                m_s[row] = newm;
                c_s[row] = c;
            }
        }
        __syncthreads();

        // rescale O then O += P V
        {
            int q = lane >> 2;
            #pragma unroll
            for (int mi = 0; mi < 2; mi++) {
                float c0 = c_s[wm + mi * 16 + q];
                float c1 = c_s[wm + mi * 16 + q + 8];
                #pragma unroll
                for (int ni = 0; ni < 4; ni++) {
                    oacc[mi][ni][0] *= c0; oacc[mi][ni][1] *= c0;
                    oacc[mi][ni][2] *= c1; oacc[mi][ni][3] *= c1;
                }
            }
        }
        #pragma unroll
        for (int kk = 0; kk < 64; kk += 16) {
            unsigned af[2][4];
            #pragma unroll
            for (int mi = 0; mi < 2; mi++)
                ldsm4(af[mi], pB + (unsigned)((wm + mi * 16) * FSTR + kk + offL) * 2u);
            #pragma unroll
            for (int g = 0; g < 2; g++) {
                unsigned bf[4];
                ldsm4t(bf, vB + (unsigned)(kk * FSTR + wn + g * 16 + offV) * 2u);
                #pragma unroll
                for (int mi = 0; mi < 2; mi++) {
                    mma16(oacc[mi][2 * g],     af[mi], bf[0], bf[2]);
                    mma16(oacc[mi][2 * g + 1], af[mi], bf[1], bf[3]);
                }
            }
        }
        __syncthreads();
    }

    // finalize: O /= l, write fp16
    {
        int q = lane >> 2, r2c = (lane & 3) * 2;
        #pragma unroll
        for (int mi = 0; mi < 2; mi++) {
            int row = wm + mi * 16 + q;
            float i0 = 1.0f / l_s[row];
            float i1 = 1.0f / l_s[row + 8];
            #pragma unroll
            for (int ni = 0; ni < 4; ni++) {
                int col = h * 64 + wn + ni * 8 + r2c;
                size_t g0 = (size_t)(b * SEQ + qrow0 + row) * D_MODEL + col;
                size_t g1 = (size_t)(b * SEQ + qrow0 + row + 8) * D_MODEL + col;
                ((__half2*)O)[g0 >> 1] = __floats2half2_rn(oacc[mi][ni][0] * i0, oacc[mi][ni][1] * i0);
                ((__half2*)O)[g1 >> 1] = __floats2half2_rn(oacc[mi][ni][2] * i1, oacc[mi][ni][3] * i1);
            }
        }
    }
}

// ---------------------------------------------------------------------------
// Reductions / LN / copies
// ---------------------------------------------------------------------------
__device__ __forceinline__ float block_reduce_sum(float val, float* sdata) {
    int t = threadIdx.x;
    #pragma unroll
    for (int off = 16; off > 0; off >>= 1)
        val += __shfl_down_sync(0xffffffff, val, off);
    if ((t & 31) == 0) sdata[t >> 5] = val;
    __syncthreads();
    if (t < 32) {
        float v = (t < 8) ? sdata[t] : 0.0f;
        #pragma unroll
        for (int off = 4; off > 0; off >>= 1)
            v += __shfl_down_sync(0xffffffff, v, off);
        if (t == 0) sdata[0] = v;
    }
    __syncthreads();
    float r = sdata[0];
    __syncthreads();
    return r;
}

__global__ __launch_bounds__(256)
void ln_kernel(const float* __restrict__ x, const float* __restrict__ g,
               const float* __restrict__ bb, float* __restrict__ outf,
               __half* __restrict__ outh) {
    __shared__ float sdata[32];
    int row = blockIdx.x;
    int t = threadIdx.x;
    const float* xr = x + (size_t)row * D_MODEL;
    float v[4];
    #pragma unroll
    for (int i = 0; i < 4; i++) v[i] = xr[t + 256 * i];
    float s = v[0] + v[1] + v[2] + v[3];
    float mu = block_reduce_sum(s, sdata) * (1.0f / 1024.0f);
    float sq = 0.f;
    #pragma unroll
    for (int i = 0; i < 4; i++) { float d0 = v[i] - mu; sq += d0 * d0; }
    float var = block_reduce_sum(sq, sdata) * (1.0f / 1024.0f);
    float inv = 1.0f / sqrtf(var + 1e-5f);
    #pragma unroll
    for (int i = 0; i < 4; i++) {
        int c = t + 256 * i;
        float o = (v[i] - mu) * inv * g[c] + bb[c];
        outf[(size_t)row * D_MODEL + c] = o;
        if (outh) outh[(size_t)row * D_MODEL + c] = __float2half(o);
    }
}

__global__ __launch_bounds__(256)
void ln_ln_kernel(const float* __restrict__ proj,
                  const float* __restrict__ g1, const float* __restrict__ b1,
                  const float* __restrict__ hids,
                  const float* __restrict__ g2, const float* __restrict__ b2,
                  float* __restrict__ outf, __half* __restrict__ outh) {
    __shared__ float sdata[32];
    int row = blockIdx.x;
    int t = threadIdx.x;
    const float* xr = proj + (size_t)row * D_MODEL;
    const float* hr = hids + (size_t)row * D_MODEL;
    float v[4], hv[4];
    #pragma unroll
    for (int i = 0; i < 4; i++) { v[i] = xr[t + 256 * i]; hv[i] = hr[t + 256 * i]; }
    float s = v[0] + v[1] + v[2] + v[3];
    float mu = block_reduce_sum(s, sdata) * (1.0f / 1024.0f);
    float sq = 0.f;
    #pragma unroll
    for (int i = 0; i < 4; i++) { float d0 = v[i] - mu; sq += d0 * d0; }
    float var = block_reduce_sum(sq, sdata) * (1.0f / 1024.0f);
    float inv = 1.0f / sqrtf(var + 1e-5f);
    float y[4];
    #pragma unroll
    for (int i = 0; i < 4; i++) {
        int c = t + 256 * i;
        y[i] = hv[i] + (v[i] - mu) * inv * g1[c] + b1[c];
    }
    float s2 = y[0] + y[1] + y[2] + y[3];
    float mu2 = block_reduce_sum(s2, sdata) * (1.0f / 1024.0f);
    float sq2 = 0.f;
    #pragma unroll
    for (int i = 0; i < 4; i++) { float d0 = y[i] - mu2; sq2 += d0 * d0; }
    float var2 = block_reduce_sum(sq2, sdata) * (1.0f / 1024.0f);
    float inv2 = 1.0f / sqrtf(var2 + 1e-5f);
    #pragma unroll
    for (int i = 0; i < 4; i++) {
        int c = t + 256 * i;
        float o = (y[i] - mu2) * inv2 * g2[c] + b2[c];
        outf[(size_t)row * D_MODEL + c] = o;
        outh[(size_t)row * D_MODEL + c] = __float2half(o);
    }
}

__global__ void copy_mem_kernel(const float* __restrict__ hids, float* __restrict__ dst) {
    int idx = blockIdx.x * 1024 + threadIdx.x;
    int b = idx >> 14;
    int rem = idx & 16383;
    int mrow = rem >> 10;
    int d = rem & 1023;
    dst[idx] = hids[((size_t)(b * SEQ + 1008 + mrow)) * D_MODEL + d];
}

// ---------------------------------------------------------------------------
static float *s_hids0 = 0, *s_proj = 0, *s_hids = 0, *s_outattn = 0;
static __half *s_h0h = 0, *s_qkvh = 0, *s_attnh = 0, *s_hidsh = 0, *s_outh = 0;
static __half *s_wTa = 0, *s_wTo = 0, *s_wTaow = 0, *s_wToow = 0, *s_wTff2 = 0;

static void resolve_scratch() {
    if (s_hids0) return;
    cudaGetSymbolAddress((void**)&s_hids0,   g_hids0);
    cudaGetSymbolAddress((void**)&s_proj,    g_proj);
    cudaGetSymbolAddress((void**)&s_hids,    g_hids);
    cudaGetSymbolAddress((void**)&s_outattn, g_outattn);
    cudaGetSymbolAddress((void**)&s_h0h,     g_h0h);
    cudaGetSymbolAddress((void**)&s_qkvh,    g_qkvh);
    cudaGetSymbolAddress((void**)&s_attnh,   g_attnh);
    cudaGetSymbolAddress((void**)&s_hidsh,   g_hidsh);
    cudaGetSymbolAddress((void**)&s_outh,    g_outh);
    cudaGetSymbolAddress((void**)&s_wTa,     g_wTa);
    cudaGetSymbolAddress((void**)&s_wTo,     g_wTo);
    cudaGetSymbolAddress((void**)&s_wTaow,   g_wTaow);
    cudaGetSymbolAddress((void**)&s_wToow,   g_wToow);
    cudaGetSymbolAddress((void**)&s_wTff2,   g_wTff2);
    cudaFuncSetAttribute(gemm_h<false>, cudaFuncAttributeMaxDynamicSharedMemorySize, GSMEM);
    cudaFuncSetAttribute(gemm_h<true>,  cudaFuncAttributeMaxDynamicSharedMemorySize, GSMEM);
    cudaFuncSetAttribute(flash_h, cudaFuncAttributeMaxDynamicSharedMemorySize, FA_SMEM);
}

static void run_attention(const __half* xh, const __half* wT, int extraFlag) {
    gemm_h<true><<<dim3(24, 32), 256, GSMEM>>>(
        xh, wT, nullptr, s_qkvh, 1024, 1024, 1024, 3072);
    flash_h<<<dim3(8, BATCH * NHEAD), 256, FA_SMEM>>>(s_qkvh, s_attnh, extraFlag);
}

extern "C" void kernel_launch(void* const* d_in, const int* in_sizes, int n_in,
                              void* d_out, int out_size) {
    const int*   data  = (const int*)d_in[0];
    const float* emb   = (const float*)d_in[2];
    const float* a_qw  = (const float*)d_in[3];
    const float* a_kvw = (const float*)d_in[4];
    const float* a_ow  = (const float*)d_in[5];
    const float* a_g   = (const float*)d_in[6];
    const float* a_b   = (const float*)d_in[7];
    const float* o_qw  = (const float*)d_in[16];
    const float* o_kvw = (const float*)d_in[17];
    const float* o_ow  = (const float*)d_in[18];
    const float* o_g   = (const float*)d_in[19];
    const float* o_b   = (const float*)d_in[20];
    const float* ff2_w = (const float*)d_in[21];
    const float* ln1_g = (const float*)d_in[22];
    const float* ln1_b = (const float*)d_in[23];
    const float* ln2_g = (const float*)d_in[24];
    const float* ln2_b = (const float*)d_in[25];
    float* out = (float*)d_out;

    resolve_scratch();

    TpArgs tp;
    tp.src[0] = a_qw;          tp.dst[0] = s_wTa;               tp.ld[0] = 1024;
    tp.src[1] = a_kvw;         tp.dst[1] = s_wTa + 1024*1024;   tp.ld[1] = 2048;
    tp.src[2] = a_kvw + 1024;  tp.dst[2] = s_wTa + 2*1024*1024; tp.ld[2] = 2048;
    tp.src[3] = o_qw;          tp.dst[3] = s_wTo;               tp.ld[3] = 1024;
    tp.src[4] = o_kvw;         tp.dst[4] = s_wTo + 1024*1024;   tp.ld[4] = 2048;
    tp.src[5] = o_kvw + 1024;  tp.dst[5] = s_wTo + 2*1024*1024; tp.ld[5] = 2048;
    tp.src[6] = a_ow;          tp.dst[6] = s_wTaow;             tp.ld[6] = 1024;
    tp.src[7] = o_ow;          tp.dst[7] = s_wToow;             tp.ld[7] = 1024;
    tp.src[8] = ff2_w;         tp.dst[8] = s_wTff2;             tp.ld[8] = 1024;
    transpose_h_kernel<<<dim3(32, 32, 9), dim3(32, 8)>>>(tp);

    embed_kernel<<<OUT_MAIN / 256, 256>>>(data, emb, s_hids0, s_h0h);

    // self attention (layer)
    run_attention(s_h0h, s_wTa, 0);
    gemm_h<false><<<dim3(8, 32), 256, GSMEM>>>(
        s_attnh, s_wTaow, s_hids0, s_proj, 1024, 1024, 1024, 1024);
    ln_kernel<<<MROWS, 256>>>(s_proj, a_g, a_b, s_hids, s_hidsh);

    copy_mem_kernel<<<64, 1024>>>(s_hids, out + OUT_MAIN);

    // OutputAttn (keys >= 1008 double-weighted)
    run_attention(s_hidsh, s_wTo, 1);
    gemm_h<false><<<dim3(8, 32), 256, GSMEM>>>(
        s_attnh, s_wToow, s_hids, s_proj, 1024, 1024, 1024, 1024);
    ln_ln_kernel<<<MROWS, 256>>>(s_proj, o_g, o_b, s_hids, ln1_g, ln1_b, s_outattn, s_outh);

    gemm_h<false><<<dim3(8, 32), 256, GSMEM>>>(
        s_outh, s_wTff2, s_outattn, s_proj, 1024, 1024, 1024, 1024);
    ln_kernel<<<MROWS, 256>>>(s_proj, ln2_g, ln2_b, out, nullptr);
}

// round 10
// speedup vs baseline: 8.9592x; 1.1204x over previous
#include <cuda_runtime.h>
#include <cuda_fp16.h>
#include <math.h>

// ---------------------------------------------------------------------------
// MemTransformerLMEncoder - fp16 mma.sync; register-resident-P flash attention.
// Dead code: UpdateAttn branch + mem input unused. new_mem = hids[:,1008:1024].
// OutputAttn = 1024-key softmax with keys >=1008 double-weighted.
// tcgen05 unavailable (harness PTX targets sm_103, not sm_103a) - mma.sync path.
// ---------------------------------------------------------------------------

#define D_MODEL 1024
#define SEQ     1024
#define BATCH   4
#define NHEAD   16
#define DHEAD   64
#define MROWS   (BATCH*SEQ)            // 4096
#define OUT_MAIN (BATCH*SEQ*D_MODEL)   // 4194304

// fp32 scratch
__device__ float g_hids0[MROWS*D_MODEL];
__device__ float g_proj[MROWS*D_MODEL];
__device__ float g_hids[MROWS*D_MODEL];
__device__ float g_outattn[MROWS*D_MODEL];
__device__ float g_pos[SEQ*D_MODEL];
// fp16 scratch
__device__ __half g_h0h[MROWS*D_MODEL];
__device__ __half g_qkvh[MROWS*3*D_MODEL];
__device__ __half g_attnh[MROWS*D_MODEL];
__device__ __half g_hidsh[MROWS*D_MODEL];
__device__ __half g_outh[MROWS*D_MODEL];
// fp16 transposed weights
__device__ __half g_wTa[3*D_MODEL*D_MODEL];
__device__ __half g_wTo[3*D_MODEL*D_MODEL];
__device__ __half g_wTaow[D_MODEL*D_MODEL];
__device__ __half g_wToow[D_MODEL*D_MODEL];
__device__ __half g_wTff2[D_MODEL*D_MODEL];

// ---------------------------------------------------------------------------
__device__ __forceinline__ void mma16(float* c, const unsigned* a, unsigned b0, unsigned b1) {
    asm volatile(
        "mma.sync.aligned.m16n8k16.row.col.f32.f16.f16.f32 "
        "{%0,%1,%2,%3}, {%4,%5,%6,%7}, {%8,%9}, {%0,%1,%2,%3};"
        : "+f"(c[0]), "+f"(c[1]), "+f"(c[2]), "+f"(c[3])
        : "r"(a[0]), "r"(a[1]), "r"(a[2]), "r"(a[3]), "r"(b0), "r"(b1));
}
__device__ __forceinline__ void ldsm4(unsigned* r, unsigned addr) {
    asm volatile("ldmatrix.sync.aligned.m8n8.x4.shared.b16 {%0,%1,%2,%3}, [%4];"
        : "=r"(r[0]), "=r"(r[1]), "=r"(r[2]), "=r"(r[3]) : "r"(addr));
}
__device__ __forceinline__ void ldsm4t(unsigned* r, unsigned addr) {
    asm volatile("ldmatrix.sync.aligned.m8n8.x4.trans.shared.b16 {%0,%1,%2,%3}, [%4];"
        : "=r"(r[0]), "=r"(r[1]), "=r"(r[2]), "=r"(r[3]) : "r"(addr));
}
__device__ __forceinline__ void cp16(unsigned dst, const void* src) {
    asm volatile("cp.async.ca.shared.global [%0], [%1], 16;" :: "r"(dst), "l"(src));
}
__device__ __forceinline__ int off16(int lane, int STR) {
    return ((lane & 7) + ((lane >> 3) & 1) * 8) * STR + ((lane >> 4) & 1) * 8;
}
__device__ __forceinline__ int off16v(int lane, int STR) {
    return ((lane & 7) + ((lane >> 4) & 1) * 8) * STR + ((lane >> 3) & 1) * 8;
}
__device__ __forceinline__ unsigned packh2(float a, float b) {
    __half2 h = __floats2half2_rn(a, b);
    return *(unsigned*)&h;
}

// ---------------------------------------------------------------------------
// Positional table (depends only on s,d): 1M accurate sinf/cosf per launch.
// ---------------------------------------------------------------------------
__global__ void pos_kernel(float* __restrict__ pos) {
    int idx = blockIdx.x * 256 + threadIdx.x;   // 0 .. 1048575
    int d = idx & (D_MODEL - 1);
    int s = idx >> 10;
    float freq  = powf(10000.0f, -(float)(d & ~1) * (1.0f / 1024.0f));
    float angle = (float)s * freq;
    pos[idx] = (d & 1) ? cosf(angle) : sinf(angle);
}

// Embedding * sqrt(D) + pos gather -> fp32 + fp16 (pure memory op)
__global__ void embed_kernel(const int* __restrict__ data,
                             const float* __restrict__ emb,
                             const float* __restrict__ pos,
                             float* __restrict__ outf, __half* __restrict__ outh) {
    int idx = blockIdx.x * 256 + threadIdx.x;
    int d  = idx & (D_MODEL - 1);
    int bs = idx >> 10;
    int s  = bs & (SEQ - 1);
    int tok = data[bs];
    float v = emb[(size_t)tok * D_MODEL + d] * 32.0f + pos[(s << 10) + d];
    outf[idx] = v;
    outh[idx] = __float2half(v);
}

// ---------------------------------------------------------------------------
// Fused transpose+fp16 convert: 9 units of 1024x1024, dst[n*1024+k]=src[k*ld+n]
// ---------------------------------------------------------------------------
struct TpArgs {
    const float* src[9];
    __half* dst[9];
    int ld[9];
};
__global__ void transpose_h_kernel(TpArgs a) {
    __shared__ float tile[32][33];
    int u = blockIdx.z;
    const float* src = a.src[u];
    __half* dst = a.dst[u];
    int ld = a.ld[u];
    int kb = blockIdx.y * 32, nb = blockIdx.x * 32;
    int tx = threadIdx.x, ty = threadIdx.y;   // 32 x 8
    #pragma unroll
    for (int i = 0; i < 32; i += 8)
        tile[ty + i][tx] = src[(size_t)(kb + ty + i) * ld + nb + tx];
    __syncthreads();
    #pragma unroll
    for (int i = 0; i < 32; i += 8)
        dst[(size_t)(nb + ty + i) * 1024 + kb + tx] = __float2half(tile[tx][ty + i]);
}

// ---------------------------------------------------------------------------
// fp16 GEMM (round-8 proven): C[M,N] = A[M,K] @ B[N,K]^T (+fp32 resid).
// BM=128 BN=128 BK=32, 256 thr, 3-stage cp.async, ldmatrix.
// ---------------------------------------------------------------------------
#define GSTR 40
#define GAB  (128*GSTR*2)
#define GSMEM (3*2*GAB)                 // 61440

template<bool OUTH>
__global__ __launch_bounds__(256, 2)
void gemm_h(const __half* __restrict__ A, const __half* __restrict__ B,
            const float* __restrict__ resid, void* __restrict__ Cg,
            int K, int lda, int ldb, int ldc) {
    extern __shared__ __align__(16) char smraw[];
    const int tid = threadIdx.x, lane = tid & 31, warp = tid >> 5;
    const int row0 = blockIdx.y * 128, col0 = blockIdx.x * 128;
    const int wm = (warp & 3) * 32, wn = (warp >> 2) * 64;
    const unsigned smBase = (unsigned)__cvta_generic_to_shared(smraw);
    const int offL = off16(lane, GSTR);

    float acc[2][8][4];
    #pragma unroll
    for (int mi = 0; mi < 2; mi++)
        #pragma unroll
        for (int ni = 0; ni < 8; ni++)
            #pragma unroll
            for (int c = 0; c < 4; c++) acc[mi][ni][c] = 0.0f;

    const int T = K / 32;

    auto loadTile = [&](int t) {
        int buf = t % 3;
        unsigned aB = smBase + (unsigned)(buf * 2 * GAB);
        unsigned bB = aB + GAB;
        const __half* Asrc = A + (size_t)row0 * lda + t * 32;
        const __half* Bsrc = B + (size_t)col0 * ldb + t * 32;
        #pragma unroll
        for (int s = 0; s < 2; s++) {
            int c = tid + 256 * s;
            int m = c >> 2, kc = (c & 3) * 8;
            cp16(aB + (unsigned)(m * GSTR + kc) * 2u, Asrc + (size_t)m * lda + kc);
        }
        #pragma unroll
        for (int s = 0; s < 2; s++) {
            int c = tid + 256 * s;
            int n = c >> 2, kc = (c & 3) * 8;
            cp16(bB + (unsigned)(n * GSTR + kc) * 2u, Bsrc + (size_t)n * ldb + kc);
        }
    };

    loadTile(0);
    asm volatile("cp.async.commit_group;" ::: "memory");
    loadTile(1);
    asm volatile("cp.async.commit_group;" ::: "memory");

    for (int t = 0; t < T; t++) {
        if (t + 2 < T) {
            loadTile(t + 2);
            asm volatile("cp.async.commit_group;" ::: "memory");
            asm volatile("cp.async.wait_group 2;" ::: "memory");
        } else if (t + 1 < T) {
            asm volatile("cp.async.wait_group 1;" ::: "memory");
        } else {
            asm volatile("cp.async.wait_group 0;" ::: "memory");
        }
        __syncthreads();

        int buf = t % 3;
        unsigned aB = smBase + (unsigned)(buf * 2 * GAB);
        unsigned bB = aB + GAB;
        #pragma unroll
        for (int kk = 0; kk < 32; kk += 16) {
            unsigned af[2][4];
            #pragma unroll
            for (int mi = 0; mi < 2; mi++)
                ldsm4(af[mi], aB + (unsigned)((wm + mi * 16) * GSTR + kk + offL) * 2u);
            #pragma unroll
            for (int g = 0; g < 4; g++) {
                unsigned bf[4];
                ldsm4(bf, bB + (unsigned)((wn + g * 16) * GSTR + kk + offL) * 2u);
                #pragma unroll
                for (int mi = 0; mi < 2; mi++) {
                    mma16(acc[mi][2 * g],     af[mi], bf[0], bf[2]);
                    mma16(acc[mi][2 * g + 1], af[mi], bf[1], bf[3]);
                }
            }
        }
        __syncthreads();
    }

    {
        int q = lane >> 2, r2 = (lane & 3) * 2;
        #pragma unroll
        for (int mi = 0; mi < 2; mi++) {
            int row = row0 + wm + mi * 16 + q;
            #pragma unroll
            for (int ni = 0; ni < 8; ni++) {
                int col = col0 + wn + ni * 8 + r2;
                float v0 = acc[mi][ni][0], v1 = acc[mi][ni][1];
                float v2 = acc[mi][ni][2], v3 = acc[mi][ni][3];
                if (resid) {
                    float2 r0 = *(const float2*)&resid[(size_t)row * ldc + col];
                    float2 r1 = *(const float2*)&resid[(size_t)(row + 8) * ldc + col];
                    v0 += r0.x; v1 += r0.y; v2 += r1.x; v3 += r1.y;
                }
                if (OUTH) {
                    __half2* C = (__half2*)Cg;
                    C[((size_t)row * ldc + col) >> 1]       = __floats2half2_rn(v0, v1);
                    C[((size_t)(row + 8) * ldc + col) >> 1] = __floats2half2_rn(v2, v3);
                } else {
                    float* C = (float*)Cg;
                    *(float2*)&C[(size_t)row * ldc + col]       = make_float2(v0, v1);
                    *(float2*)&C[(size_t)(row + 8) * ldc + col] = make_float2(v2, v3);
                }
            }
        }
    }
}

// ---------------------------------------------------------------------------
// Flash attention, register-resident P. grid=(SEQ/128, B*H), 256 thr.
// Each warp owns 16 query rows x ALL 64 keys: softmax fully warp-local
// (4-lane shfl reductions, m/l in registers). S C-fragments are repacked
// in-register to P A-fragments (m16n8 C layout == m16k16 A layout).
// smem: Q 128x64 + double-buffered K/V 64x64 (stride 72 halves).
// ---------------------------------------------------------------------------
#define FSTR 72
#define FKH  9216                       // halves
#define FVH  18432
#define FKVB 4608
#define FA_SMEM 55296                   // (9216 + 2*4608 + 2*4608) * 2 bytes

__global__ __launch_bounds__(256, 2)
void flash_h(const __half* __restrict__ qkv, __half* __restrict__ O, int extraFlag) {
    extern __shared__ __align__(16) char smraw[];
    const int tid = threadIdx.x, lane = tid & 31, warp = tid >> 5;
    const int wm = warp * 16;
    const int qb = blockIdx.x, bh = blockIdx.y;
    const int b = bh >> 4, h = bh & 15;
    const int qrow0 = qb * 128;

    const unsigned smBase = (unsigned)__cvta_generic_to_shared(smraw);
    const int offL = off16(lane, FSTR);
    const int offV = off16v(lane, FSTR);

    const __half* base = qkv + (size_t)(b * SEQ) * 3072 + h * 64;

    // load Q tile 128x64
    {
        const __half* Qsrc = base + (size_t)qrow0 * 3072;
        #pragma unroll
        for (int s = 0; s < 4; s++) {
            int c = tid + 256 * s;
            int m = c >> 3, kc = (c & 7) * 8;
            cp16(smBase + (unsigned)(m * FSTR + kc) * 2u, Qsrc + (size_t)m * 3072 + kc);
        }
    }
    auto loadKV = [&](int t) {
        int buf = t & 1;
        unsigned kB = smBase + (unsigned)(FKH + buf * FKVB) * 2u;
        unsigned vB = smBase + (unsigned)(FVH + buf * FKVB) * 2u;
        const __half* Ksrc = base + (size_t)(t * 64) * 3072 + 1024;
        const __half* Vsrc = base + (size_t)(t * 64) * 3072 + 2048;
        #pragma unroll
        for (int s = 0; s < 2; s++) {
            int c = tid + 256 * s;
            int n = c >> 3, kc = (c & 7) * 8;
            cp16(kB + (unsigned)(n * FSTR + kc) * 2u, Ksrc + (size_t)n * 3072 + kc);
            cp16(vB + (unsigned)(n * FSTR + kc) * 2u, Vsrc + (size_t)n * 3072 + kc);
        }
    };
    loadKV(0);
    asm volatile("cp.async.commit_group;" ::: "memory");

    float m0 = -INFINITY, m1 = -INFINITY, l0 = 0.0f, l1 = 0.0f;
    float oacc[8][4];
    #pragma unroll
    for (int ni = 0; ni < 8; ni++)
        #pragma unroll
        for (int c = 0; c < 4; c++) oacc[ni][c] = 0.0f;

    for (int t = 0; t < 16; t++) {
        if (t + 1 < 16) {
            loadKV(t + 1);
            asm volatile("cp.async.commit_group;" ::: "memory");
            asm volatile("cp.async.wait_group 1;" ::: "memory");
        } else {
            asm volatile("cp.async.wait_group 0;" ::: "memory");
        }
        __syncthreads();

        int buf = t & 1;
        unsigned kB = smBase + (unsigned)(FKH + buf * FKVB) * 2u;
        unsigned vB = smBase + (unsigned)(FVH + buf * FKVB) * 2u;

        // S = Q K^T : 16 rows x 64 keys per warp, in registers
        float sc[8][4];
        #pragma unroll
        for (int ni = 0; ni < 8; ni++)
            #pragma unroll
            for (int c = 0; c < 4; c++) sc[ni][c] = 0.0f;
        #pragma unroll
        for (int kki = 0; kki < 4; kki++) {
            int kk = kki * 16;
            unsigned af[4];
            ldsm4(af, smBase + (unsigned)(wm * FSTR + kk + offL) * 2u);
            #pragma unroll
            for (int g = 0; g < 4; g++) {
                unsigned bf[4];
                ldsm4(bf, kB + (unsigned)((g * 16) * FSTR + kk + offL) * 2u);
                mma16(sc[2 * g],     af, bf[0], bf[2]);
                mma16(sc[2 * g + 1], af, bf[1], bf[3]);
            }
        }

        // warp-local online softmax
        float rm0 = -INFINITY, rm1 = -INFINITY;
        #pragma unroll
        for (int ni = 0; ni < 8; ni++) {
            sc[ni][0] *= 0.125f; sc[ni][1] *= 0.125f;
            sc[ni][2] *= 0.125f; sc[ni][3] *= 0.125f;
            rm0 = fmaxf(rm0, fmaxf(sc[ni][0], sc[ni][1]));
            rm1 = fmaxf(rm1, fmaxf(sc[ni][2], sc[ni][3]));
        }
        rm0 = fmaxf(rm0, __shfl_xor_sync(0xffffffff, rm0, 1));
        rm0 = fmaxf(rm0, __shfl_xor_sync(0xffffffff, rm0, 2));
        rm1 = fmaxf(rm1, __shfl_xor_sync(0xffffffff, rm1, 1));
        rm1 = fmaxf(rm1, __shfl_xor_sync(0xffffffff, rm1, 2));
        float nm0 = fmaxf(m0, rm0), nm1 = fmaxf(m1, rm1);
        float c0 = __expf(m0 - nm0), c1 = __expf(m1 - nm1);
        m0 = nm0; m1 = nm1;
        float s0 = 0.0f, s1 = 0.0f;
        bool dbl = extraFlag && (t == 15);
        #pragma unroll
        for (int ni = 0; ni < 8; ni++) {
            float p00 = __expf(sc[ni][0] - nm0);
            float p01 = __expf(sc[ni][1] - nm0);
            float p10 = __expf(sc[ni][2] - nm1);
            float p11 = __expf(sc[ni][3] - nm1);
            if (dbl && ni >= 6) { p00 *= 2.f; p01 *= 2.f; p10 *= 2.f; p11 *= 2.f; }
            s0 += p00 + p01; s1 += p10 + p11;
            sc[ni][0] = p00; sc[ni][1] = p01; sc[ni][2] = p10; sc[ni][3] = p11;
        }
        s0 += __shfl_xor_sync(0xffffffff, s0, 1);
        s0 += __shfl_xor_sync(0xffffffff, s0, 2);
        s1 += __shfl_xor_sync(0xffffffff, s1, 1);
        s1 += __shfl_xor_sync(0xffffffff, s1, 2);
        l0 = l0 * c0 + s0;
        l1 = l1 * c1 + s1;

        // rescale O, then O += P V (P packed from registers)
        #pragma unroll
        for (int ni = 0; ni < 8; ni++) {
            oacc[ni][0] *= c0; oacc[ni][1] *= c0;
            oacc[ni][2] *= c1; oacc[ni][3] *= c1;
        }
        #pragma unroll
        for (int kki = 0; kki < 4; kki++) {
            int ni0 = 2 * kki;
            unsigned af2[4];
            af2[0] = packh2(sc[ni0][0],     sc[ni0][1]);
            af2[1] = packh2(sc[ni0][2],     sc[ni0][3]);
            af2[2] = packh2(sc[ni0 + 1][0], sc[ni0 + 1][1]);
            af2[3] = packh2(sc[ni0 + 1][2], sc[ni0 + 1][3]);
            #pragma unroll
            for (int g = 0; g < 4; g++) {
                unsigned bf[4];
                ldsm4t(bf, vB + (unsigned)((kki * 16) * FSTR + g * 16 + offV) * 2u);
                mma16(oacc[2 * g],     af2, bf[0], bf[2]);
                mma16(oacc[2 * g + 1], af2, bf[1], bf[3]);
            }
        }
        __syncthreads();
    }

    // finalize: O /= l, write fp16
    {
        int q = lane >> 2, r2c = (lane & 3) * 2;
        float i0 = 1.0f / l0, i1 = 1.0f / l1;
        int row0 = qrow0 + wm + q;
        #pragma unroll
        for (int ni = 0; ni < 8; ni++) {
            int col = h * 64 + ni * 8 + r2c;
            size_t g0 = (size_t)(b * SEQ + row0) * D_MODEL + col;
            size_t g1 = (size_t)(b * SEQ + row0 + 8) * D_MODEL + col;
            ((__half2*)O)[g0 >> 1] = __floats2half2_rn(oacc[ni][0] * i0, oacc[ni][1] * i0);
            ((__half2*)O)[g1 >> 1] = __floats2half2_rn(oacc[ni][2] * i1, oacc[ni][3] * i1);
        }
    }
}

// ---------------------------------------------------------------------------
// Reductions / LN / copies
// ---------------------------------------------------------------------------
__device__ __forceinline__ float block_reduce_sum(float val, float* sdata) {
    int t = threadIdx.x;
    #pragma unroll
    for (int off = 16; off > 0; off >>= 1)
        val += __shfl_down_sync(0xffffffff, val, off);
    if ((t & 31) == 0) sdata[t >> 5] = val;
    __syncthreads();
    if (t < 32) {
        float v = (t < 8) ? sdata[t] : 0.0f;
        #pragma unroll
        for (int off = 4; off > 0; off >>= 1)
            v += __shfl_down_sync(0xffffffff, v, off);
        if (t == 0) sdata[0] = v;
    }
    __syncthreads();
    float r = sdata[0];
    __syncthreads();
    return r;
}

__global__ __launch_bounds__(256)
void ln_kernel(const float* __restrict__ x, const float* __restrict__ g,
               const float* __restrict__ bb, float* __restrict__ outf,
               __half* __restrict__ outh) {
    __shared__ float sdata[32];
    int row = blockIdx.x;
    int t = threadIdx.x;
    const float* xr = x + (size_t)row * D_MODEL;
    float v[4];
    #pragma unroll
    for (int i = 0; i < 4; i++) v[i] = xr[t + 256 * i];
    float s = v[0] + v[1] + v[2] + v[3];
    float mu = block_reduce_sum(s, sdata) * (1.0f / 1024.0f);
    float sq = 0.f;
    #pragma unroll
    for (int i = 0; i < 4; i++) { float d0 = v[i] - mu; sq += d0 * d0; }
    float var = block_reduce_sum(sq, sdata) * (1.0f / 1024.0f);
    float inv = 1.0f / sqrtf(var + 1e-5f);
    #pragma unroll
    for (int i = 0; i < 4; i++) {
        int c = t + 256 * i;
        float o = (v[i] - mu) * inv * g[c] + bb[c];
        outf[(size_t)row * D_MODEL + c] = o;
        if (outh) outh[(size_t)row * D_MODEL + c] = __float2half(o);
    }
}

__global__ __launch_bounds__(256)
void ln_ln_kernel(const float* __restrict__ proj,
                  const float* __restrict__ g1, const float* __restrict__ b1,
                  const float* __restrict__ hids,
                  const float* __restrict__ g2, const float* __restrict__ b2,
                  float* __restrict__ outf, __half* __restrict__ outh) {
    __shared__ float sdata[32];
    int row = blockIdx.x;
    int t = threadIdx.x;
    const float* xr = proj + (size_t)row * D_MODEL;
    const float* hr = hids + (size_t)row * D_MODEL;
    float v[4], hv[4];
    #pragma unroll
    for (int i = 0; i < 4; i++) { v[i] = xr[t + 256 * i]; hv[i] = hr[t + 256 * i]; }
    float s = v[0] + v[1] + v[2] + v[3];
    float mu = block_reduce_sum(s, sdata) * (1.0f / 1024.0f);
    float sq = 0.f;
    #pragma unroll
    for (int i = 0; i < 4; i++) { float d0 = v[i] - mu; sq += d0 * d0; }
    float var = block_reduce_sum(sq, sdata) * (1.0f / 1024.0f);
    float inv = 1.0f / sqrtf(var + 1e-5f);
    float y[4];
    #pragma unroll
    for (int i = 0; i < 4; i++) {
        int c = t + 256 * i;
        y[i] = hv[i] + (v[i] - mu) * inv * g1[c] + b1[c];
    }
    float s2 = y[0] + y[1] + y[2] + y[3];
    float mu2 = block_reduce_sum(s2, sdata) * (1.0f / 1024.0f);
    float sq2 = 0.f;
    #pragma unroll
    for (int i = 0; i < 4; i++) { float d0 = y[i] - mu2; sq2 += d0 * d0; }
    float var2 = block_reduce_sum(sq2, sdata) * (1.0f / 1024.0f);
    float inv2 = 1.0f / sqrtf(var2 + 1e-5f);
    #pragma unroll
    for (int i = 0; i < 4; i++) {
        int c = t + 256 * i;
        float o = (y[i] - mu2) * inv2 * g2[c] + b2[c];
        outf[(size_t)row * D_MODEL + c] = o;
        outh[(size_t)row * D_MODEL + c] = __float2half(o);
    }
}

__global__ void copy_mem_kernel(const float* __restrict__ hids, float* __restrict__ dst) {
    int idx = blockIdx.x * 1024 + threadIdx.x;
    int b = idx >> 14;
    int rem = idx & 16383;
    int mrow = rem >> 10;
    int d = rem & 1023;
    dst[idx] = hids[((size_t)(b * SEQ + 1008 + mrow)) * D_MODEL + d];
}

// ---------------------------------------------------------------------------
static float *s_hids0 = 0, *s_proj = 0, *s_hids = 0, *s_outattn = 0, *s_pos = 0;
static __half *s_h0h = 0, *s_qkvh = 0, *s_attnh = 0, *s_hidsh = 0, *s_outh = 0;
static __half *s_wTa = 0, *s_wTo = 0, *s_wTaow = 0, *s_wToow = 0, *s_wTff2 = 0;

static void resolve_scratch() {
    if (s_hids0) return;
    cudaGetSymbolAddress((void**)&s_hids0,   g_hids0);
    cudaGetSymbolAddress((void**)&s_proj,    g_proj);
    cudaGetSymbolAddress((void**)&s_hids,    g_hids);
    cudaGetSymbolAddress((void**)&s_outattn, g_outattn);
    cudaGetSymbolAddress((void**)&s_pos,     g_pos);
    cudaGetSymbolAddress((void**)&s_h0h,     g_h0h);
    cudaGetSymbolAddress((void**)&s_qkvh,    g_qkvh);
    cudaGetSymbolAddress((void**)&s_attnh,   g_attnh);
    cudaGetSymbolAddress((void**)&s_hidsh,   g_hidsh);
    cudaGetSymbolAddress((void**)&s_outh,    g_outh);
    cudaGetSymbolAddress((void**)&s_wTa,     g_wTa);
    cudaGetSymbolAddress((void**)&s_wTo,     g_wTo);
    cudaGetSymbolAddress((void**)&s_wTaow,   g_wTaow);
    cudaGetSymbolAddress((void**)&s_wToow,   g_wToow);
    cudaGetSymbolAddress((void**)&s_wTff2,   g_wTff2);
    cudaFuncSetAttribute(gemm_h<false>, cudaFuncAttributeMaxDynamicSharedMemorySize, GSMEM);
    cudaFuncSetAttribute(gemm_h<true>,  cudaFuncAttributeMaxDynamicSharedMemorySize, GSMEM);
    cudaFuncSetAttribute(flash_h, cudaFuncAttributeMaxDynamicSharedMemorySize, FA_SMEM);
}

static void run_attention(const __half* xh, const __half* wT, int extraFlag) {
    gemm_h<true><<<dim3(24, 32), 256, GSMEM>>>(
        xh, wT, nullptr, s_qkvh, 1024, 1024, 1024, 3072);
    flash_h<<<dim3(8, BATCH * NHEAD), 256, FA_SMEM>>>(s_qkvh, s_attnh, extraFlag);
}

extern "C" void kernel_launch(void* const* d_in, const int* in_sizes, int n_in,
                              void* d_out, int out_size) {
    const int*   data  = (const int*)d_in[0];
    const float* emb   = (const float*)d_in[2];
    const float* a_qw  = (const float*)d_in[3];
    const float* a_kvw = (const float*)d_in[4];
    const float* a_ow  = (const float*)d_in[5];
    const float* a_g   = (const float*)d_in[6];
    const float* a_b   = (const float*)d_in[7];
    const float* o_qw  = (const float*)d_in[16];
    const float* o_kvw = (const float*)d_in[17];
    const float* o_ow  = (const float*)d_in[18];
    const float* o_g   = (const float*)d_in[19];
    const float* o_b   = (const float*)d_in[20];
    const float* ff2_w = (const float*)d_in[21];
    const float* ln1_g = (const float*)d_in[22];
    const float* ln1_b = (const float*)d_in[23];
    const float* ln2_g = (const float*)d_in[24];
    const float* ln2_b = (const float*)d_in[25];
    float* out = (float*)d_out;

    resolve_scratch();

    TpArgs tp;
    tp.src[0] = a_qw;          tp.dst[0] = s_wTa;               tp.ld[0] = 1024;
    tp.src[1] = a_kvw;         tp.dst[1] = s_wTa + 1024*1024;   tp.ld[1] = 2048;
    tp.src[2] = a_kvw + 1024;  tp.dst[2] = s_wTa + 2*1024*1024; tp.ld[2] = 2048;
    tp.src[3] = o_qw;          tp.dst[3] = s_wTo;               tp.ld[3] = 1024;
    tp.src[4] = o_kvw;         tp.dst[4] = s_wTo + 1024*1024;   tp.ld[4] = 2048;
    tp.src[5] = o_kvw + 1024;  tp.dst[5] = s_wTo + 2*1024*1024; tp.ld[5] = 2048;
    tp.src[6] = a_ow;          tp.dst[6] = s_wTaow;             tp.ld[6] = 1024;
    tp.src[7] = o_ow;          tp.dst[7] = s_wToow;             tp.ld[7] = 1024;
    tp.src[8] = ff2_w;         tp.dst[8] = s_wTff2;             tp.ld[8] = 1024;
    transpose_h_kernel<<<dim3(32, 32, 9), dim3(32, 8)>>>(tp);

    pos_kernel<<<(SEQ * D_MODEL) / 256, 256>>>(s_pos);
    embed_kernel<<<OUT_MAIN / 256, 256>>>(data, emb, s_pos, s_hids0, s_h0h);

    // self attention (layer)
    run_attention(s_h0h, s_wTa, 0);
    gemm_h<false><<<dim3(8, 32), 256, GSMEM>>>(
        s_attnh, s_wTaow, s_hids0, s_proj, 1024, 1024, 1024, 1024);
    ln_kernel<<<MROWS, 256>>>(s_proj, a_g, a_b, s_hids, s_hidsh);

    copy_mem_kernel<<<64, 1024>>>(s_hids, out + OUT_MAIN);

    // OutputAttn (keys >= 1008 double-weighted)
    run_attention(s_hidsh, s_wTo, 1);
    gemm_h<false><<<dim3(8, 32), 256, GSMEM>>>(
        s_attnh, s_wToow, s_hids, s_proj, 1024, 1024, 1024, 1024);
    ln_ln_kernel<<<MROWS, 256>>>(s_proj, o_g, o_b, s_hids, ln1_g, ln1_b, s_outattn, s_outh);

    gemm_h<false><<<dim3(8, 32), 256, GSMEM>>>(
        s_outh, s_wTff2, s_outattn, s_proj, 1024, 1024, 1024, 1024);
    ln_kernel<<<MROWS, 256>>>(s_proj, ln2_g, ln2_b, out, nullptr);
}

// round 11
// speedup vs baseline: 9.0969x; 1.0154x over previous
#include <cuda_runtime.h>
#include <cuda_fp16.h>
#include <math.h>

// ---------------------------------------------------------------------------
// MemTransformerLMEncoder - fp16 mma.sync; 64x64 warp-tile GEMM (4 warps),
// register-resident-P flash attention.
// Dead code: UpdateAttn branch + mem input unused. new_mem = hids[:,1008:1024].
// OutputAttn = 1024-key softmax with keys >=1008 double-weighted.
// tcgen05 unavailable (harness PTX targets sm_103) - mma.sync path.
// ---------------------------------------------------------------------------

#define D_MODEL 1024
#define SEQ     1024
#define BATCH   4
#define NHEAD   16
#define DHEAD   64
#define MROWS   (BATCH*SEQ)            // 4096
#define OUT_MAIN (BATCH*SEQ*D_MODEL)   // 4194304

// fp32 scratch
__device__ float g_hids0[MROWS*D_MODEL];
__device__ float g_proj[MROWS*D_MODEL];
__device__ float g_hids[MROWS*D_MODEL];
__device__ float g_outattn[MROWS*D_MODEL];
__device__ float g_pos[SEQ*D_MODEL];
// fp16 scratch
__device__ __half g_h0h[MROWS*D_MODEL];
__device__ __half g_qkvh[MROWS*3*D_MODEL];
__device__ __half g_attnh[MROWS*D_MODEL];
__device__ __half g_hidsh[MROWS*D_MODEL];
__device__ __half g_outh[MROWS*D_MODEL];
// fp16 transposed weights
__device__ __half g_wTa[3*D_MODEL*D_MODEL];
__device__ __half g_wTo[3*D_MODEL*D_MODEL];
__device__ __half g_wTaow[D_MODEL*D_MODEL];
__device__ __half g_wToow[D_MODEL*D_MODEL];
__device__ __half g_wTff2[D_MODEL*D_MODEL];

// ---------------------------------------------------------------------------
__device__ __forceinline__ void mma16(float* c, const unsigned* a, unsigned b0, unsigned b1) {
    asm volatile(
        "mma.sync.aligned.m16n8k16.row.col.f32.f16.f16.f32 "
        "{%0,%1,%2,%3}, {%4,%5,%6,%7}, {%8,%9}, {%0,%1,%2,%3};"
        : "+f"(c[0]), "+f"(c[1]), "+f"(c[2]), "+f"(c[3])
        : "r"(a[0]), "r"(a[1]), "r"(a[2]), "r"(a[3]), "r"(b0), "r"(b1));
}
__device__ __forceinline__ void ldsm4(unsigned* r, unsigned addr) {
    asm volatile("ldmatrix.sync.aligned.m8n8.x4.shared.b16 {%0,%1,%2,%3}, [%4];"
        : "=r"(r[0]), "=r"(r[1]), "=r"(r[2]), "=r"(r[3]) : "r"(addr));
}
__device__ __forceinline__ void ldsm4t(unsigned* r, unsigned addr) {
    asm volatile("ldmatrix.sync.aligned.m8n8.x4.trans.shared.b16 {%0,%1,%2,%3}, [%4];"
        : "=r"(r[0]), "=r"(r[1]), "=r"(r[2]), "=r"(r[3]) : "r"(addr));
}
__device__ __forceinline__ void cp16(unsigned dst, const void* src) {
    asm volatile("cp.async.ca.shared.global [%0], [%1], 16;" :: "r"(dst), "l"(src));
}
__device__ __forceinline__ int off16(int lane, int STR) {
    return ((lane & 7) + ((lane >> 3) & 1) * 8) * STR + ((lane >> 4) & 1) * 8;
}
__device__ __forceinline__ int off16v(int lane, int STR) {
    return ((lane & 7) + ((lane >> 4) & 1) * 8) * STR + ((lane >> 3) & 1) * 8;
}
__device__ __forceinline__ unsigned packh2(float a, float b) {
    __half2 h = __floats2half2_rn(a, b);
    return *(unsigned*)&h;
}

// ---------------------------------------------------------------------------
// Positional table (depends only on s,d).
// ---------------------------------------------------------------------------
__global__ void pos_kernel(float* __restrict__ pos) {
    int idx = blockIdx.x * 256 + threadIdx.x;
    int d = idx & (D_MODEL - 1);
    int s = idx >> 10;
    float freq  = powf(10000.0f, -(float)(d & ~1) * (1.0f / 1024.0f));
    float angle = (float)s * freq;
    pos[idx] = (d & 1) ? cosf(angle) : sinf(angle);
}

__global__ void embed_kernel(const int* __restrict__ data,
                             const float* __restrict__ emb,
                             const float* __restrict__ pos,
                             float* __restrict__ outf, __half* __restrict__ outh) {
    int idx = blockIdx.x * 256 + threadIdx.x;
    int d  = idx & (D_MODEL - 1);
    int bs = idx >> 10;
    int s  = bs & (SEQ - 1);
    int tok = data[bs];
    float v = emb[(size_t)tok * D_MODEL + d] * 32.0f + pos[(s << 10) + d];
    outf[idx] = v;
    outh[idx] = __float2half(v);
}

// ---------------------------------------------------------------------------
// Fused transpose+fp16 convert: 9 units of 1024x1024
// ---------------------------------------------------------------------------
struct TpArgs {
    const float* src[9];
    __half* dst[9];
    int ld[9];
};
__global__ void transpose_h_kernel(TpArgs a) {
    __shared__ float tile[32][33];
    int u = blockIdx.z;
    const float* src = a.src[u];
    __half* dst = a.dst[u];
    int ld = a.ld[u];
    int kb = blockIdx.y * 32, nb = blockIdx.x * 32;
    int tx = threadIdx.x, ty = threadIdx.y;
    #pragma unroll
    for (int i = 0; i < 32; i += 8)
        tile[ty + i][tx] = src[(size_t)(kb + ty + i) * ld + nb + tx];
    __syncthreads();
    #pragma unroll
    for (int i = 0; i < 32; i += 8)
        dst[(size_t)(nb + ty + i) * 1024 + kb + tx] = __float2half(tile[tx][ty + i]);
}

// ---------------------------------------------------------------------------
// fp16 GEMM, 4 warps (128 thr), 64x64 warp tiles, CTA tile 128x128, BK=32,
// 3-stage cp.async, ldmatrix. C = A[M,K] @ B[N,K]^T (+fp32 resid).
// ---------------------------------------------------------------------------
#define GSTR 40
#define GAB  (128*GSTR*2)               // bytes per A (or B) buffer = 10240
#define GSMEM (3*2*GAB)                 // 61440

template<bool OUTH>
__global__ __launch_bounds__(128, 2)
void gemm_h(const __half* __restrict__ A, const __half* __restrict__ B,
            const float* __restrict__ resid, void* __restrict__ Cg,
            int K, int lda, int ldb, int ldc) {
    extern __shared__ __align__(16) char smraw[];
    const int tid = threadIdx.x, lane = tid & 31, warp = tid >> 5;
    const int row0 = blockIdx.y * 128, col0 = blockIdx.x * 128;
    const int wm = (warp & 1) * 64, wn = (warp >> 1) * 64;
    const unsigned smBase = (unsigned)__cvta_generic_to_shared(smraw);
    const int offL = off16(lane, GSTR);

    float acc[4][8][4];
    #pragma unroll
    for (int mi = 0; mi < 4; mi++)
        #pragma unroll
        for (int ni = 0; ni < 8; ni++)
            #pragma unroll
            for (int c = 0; c < 4; c++) acc[mi][ni][c] = 0.0f;

    const int T = K / 32;

    auto loadTile = [&](int t) {
        int buf = t % 3;
        unsigned aB = smBase + (unsigned)(buf * 2 * GAB);
        unsigned bB = aB + GAB;
        const __half* Asrc = A + (size_t)row0 * lda + t * 32;
        const __half* Bsrc = B + (size_t)col0 * ldb + t * 32;
        #pragma unroll
        for (int s = 0; s < 4; s++) {
            int c = tid + 128 * s;              // 0..511
            int m = c >> 2, kc = (c & 3) * 8;
            cp16(aB + (unsigned)(m * GSTR + kc) * 2u, Asrc + (size_t)m * lda + kc);
        }
        #pragma unroll
        for (int s = 0; s < 4; s++) {
            int c = tid + 128 * s;
            int n = c >> 2, kc = (c & 3) * 8;
            cp16(bB + (unsigned)(n * GSTR + kc) * 2u, Bsrc + (size_t)n * ldb + kc);
        }
    };

    loadTile(0);
    asm volatile("cp.async.commit_group;" ::: "memory");
    loadTile(1);
    asm volatile("cp.async.commit_group;" ::: "memory");

    for (int t = 0; t < T; t++) {
        if (t + 2 < T) {
            loadTile(t + 2);
            asm volatile("cp.async.commit_group;" ::: "memory");
            asm volatile("cp.async.wait_group 2;" ::: "memory");
        } else if (t + 1 < T) {
            asm volatile("cp.async.wait_group 1;" ::: "memory");
        } else {
            asm volatile("cp.async.wait_group 0;" ::: "memory");
        }
        __syncthreads();

        int buf = t % 3;
        unsigned aB = smBase + (unsigned)(buf * 2 * GAB);
        unsigned bB = aB + GAB;
        #pragma unroll
        for (int kk = 0; kk < 32; kk += 16) {
            unsigned af[4][4];
            #pragma unroll
            for (int mi = 0; mi < 4; mi++)
                ldsm4(af[mi], aB + (unsigned)((wm + mi * 16) * GSTR + kk + offL) * 2u);
            #pragma unroll
            for (int g = 0; g < 4; g++) {
                unsigned bf[4];
                ldsm4(bf, bB + (unsigned)((wn + g * 16) * GSTR + kk + offL) * 2u);
                #pragma unroll
                for (int mi = 0; mi < 4; mi++) {
                    mma16(acc[mi][2 * g],     af[mi], bf[0], bf[2]);
                    mma16(acc[mi][2 * g + 1], af[mi], bf[1], bf[3]);
                }
            }
        }
        __syncthreads();
    }

    {
        int q = lane >> 2, r2 = (lane & 3) * 2;
        #pragma unroll
        for (int mi = 0; mi < 4; mi++) {
            int row = row0 + wm + mi * 16 + q;
            #pragma unroll
            for (int ni = 0; ni < 8; ni++) {
                int col = col0 + wn + ni * 8 + r2;
                float v0 = acc[mi][ni][0], v1 = acc[mi][ni][1];
                float v2 = acc[mi][ni][2], v3 = acc[mi][ni][3];
                if (resid) {
                    float2 r0 = *(const float2*)&resid[(size_t)row * ldc + col];
                    float2 r1 = *(const float2*)&resid[(size_t)(row + 8) * ldc + col];
                    v0 += r0.x; v1 += r0.y; v2 += r1.x; v3 += r1.y;
                }
                if (OUTH) {
                    __half2* C = (__half2*)Cg;
                    C[((size_t)row * ldc + col) >> 1]       = __floats2half2_rn(v0, v1);
                    C[((size_t)(row + 8) * ldc + col) >> 1] = __floats2half2_rn(v2, v3);
                } else {
                    float* C = (float*)Cg;
                    *(float2*)&C[(size_t)row * ldc + col]       = make_float2(v0, v1);
                    *(float2*)&C[(size_t)(row + 8) * ldc + col] = make_float2(v2, v3);
                }
            }
        }
    }
}

// ---------------------------------------------------------------------------
// Flash attention, register-resident P (round-10 proven).
// ---------------------------------------------------------------------------
#define FSTR 72
#define FKH  9216
#define FVH  18432
#define FKVB 4608
#define FA_SMEM 55296

__global__ __launch_bounds__(256, 2)
void flash_h(const __half* __restrict__ qkv, __half* __restrict__ O, int extraFlag) {
    extern __shared__ __align__(16) char smraw[];
    const int tid = threadIdx.x, lane = tid & 31, warp = tid >> 5;
    const int wm = warp * 16;
    const int qb = blockIdx.x, bh = blockIdx.y;
    const int b = bh >> 4, h = bh & 15;
    const int qrow0 = qb * 128;

    const unsigned smBase = (unsigned)__cvta_generic_to_shared(smraw);
    const int offL = off16(lane, FSTR);
    const int offV = off16v(lane, FSTR);

    const __half* base = qkv + (size_t)(b * SEQ) * 3072 + h * 64;

    {
        const __half* Qsrc = base + (size_t)qrow0 * 3072;
        #pragma unroll
        for (int s = 0; s < 4; s++) {
            int c = tid + 256 * s;
            int m = c >> 3, kc = (c & 7) * 8;
            cp16(smBase + (unsigned)(m * FSTR + kc) * 2u, Qsrc + (size_t)m * 3072 + kc);
        }
    }
    auto loadKV = [&](int t) {
        int buf = t & 1;
        unsigned kB = smBase + (unsigned)(FKH + buf * FKVB) * 2u;
        unsigned vB = smBase + (unsigned)(FVH + buf * FKVB) * 2u;
        const __half* Ksrc = base + (size_t)(t * 64) * 3072 + 1024;
        const __half* Vsrc = base + (size_t)(t * 64) * 3072 + 2048;
        #pragma unroll
        for (int s = 0; s < 2; s++) {
            int c = tid + 256 * s;
            int n = c >> 3, kc = (c & 7) * 8;
            cp16(kB + (unsigned)(n * FSTR + kc) * 2u, Ksrc + (size_t)n * 3072 + kc);
            cp16(vB + (unsigned)(n * FSTR + kc) * 2u, Vsrc + (size_t)n * 3072 + kc);
        }
    };
    loadKV(0);
    asm volatile("cp.async.commit_group;" ::: "memory");

    float m0 = -INFINITY, m1 = -INFINITY, l0 = 0.0f, l1 = 0.0f;
    float oacc[8][4];
    #pragma unroll
    for (int ni = 0; ni < 8; ni++)
        #pragma unroll
        for (int c = 0; c < 4; c++) oacc[ni][c] = 0.0f;

    for (int t = 0; t < 16; t++) {
        if (t + 1 < 16) {
            loadKV(t + 1);
            asm volatile("cp.async.commit_group;" ::: "memory");
            asm volatile("cp.async.wait_group 1;" ::: "memory");
        } else {
            asm volatile("cp.async.wait_group 0;" ::: "memory");
        }
        __syncthreads();

        int buf = t & 1;
        unsigned kB = smBase + (unsigned)(FKH + buf * FKVB) * 2u;
        unsigned vB = smBase + (unsigned)(FVH + buf * FKVB) * 2u;

        float sc[8][4];
        #pragma unroll
        for (int ni = 0; ni < 8; ni++)
            #pragma unroll
            for (int c = 0; c < 4; c++) sc[ni][c] = 0.0f;
        #pragma unroll
        for (int kki = 0; kki < 4; kki++) {
            int kk = kki * 16;
            unsigned af[4];
            ldsm4(af, smBase + (unsigned)(wm * FSTR + kk + offL) * 2u);
            #pragma unroll
            for (int g = 0; g < 4; g++) {
                unsigned bf[4];
                ldsm4(bf, kB + (unsigned)((g * 16) * FSTR + kk + offL) * 2u);
                mma16(sc[2 * g],     af, bf[0], bf[2]);
                mma16(sc[2 * g + 1], af, bf[1], bf[3]);
            }
        }

        float rm0 = -INFINITY, rm1 = -INFINITY;
        #pragma unroll
        for (int ni = 0; ni < 8; ni++) {
            sc[ni][0] *= 0.125f; sc[ni][1] *= 0.125f;
            sc[ni][2] *= 0.125f; sc[ni][3] *= 0.125f;
            rm0 = fmaxf(rm0, fmaxf(sc[ni][0], sc[ni][1]));
            rm1 = fmaxf(rm1, fmaxf(sc[ni][2], sc[ni][3]));
        }
        rm0 = fmaxf(rm0, __shfl_xor_sync(0xffffffff, rm0, 1));
        rm0 = fmaxf(rm0, __shfl_xor_sync(0xffffffff, rm0, 2));
        rm1 = fmaxf(rm1, __shfl_xor_sync(0xffffffff, rm1, 1));
        rm1 = fmaxf(rm1, __shfl_xor_sync(0xffffffff, rm1, 2));
        float nm0 = fmaxf(m0, rm0), nm1 = fmaxf(m1, rm1);
        float c0 = __expf(m0 - nm0), c1 = __expf(m1 - nm1);
        m0 = nm0; m1 = nm1;
        float s0 = 0.0f, s1 = 0.0f;
        bool dbl = extraFlag && (t == 15);
        #pragma unroll
        for (int ni = 0; ni < 8; ni++) {
            float p00 = __expf(sc[ni][0] - nm0);
            float p01 = __expf(sc[ni][1] - nm0);
            float p10 = __expf(sc[ni][2] - nm1);
            float p11 = __expf(sc[ni][3] - nm1);
            if (dbl && ni >= 6) { p00 *= 2.f; p01 *= 2.f; p10 *= 2.f; p11 *= 2.f; }
            s0 += p00 + p01; s1 += p10 + p11;
            sc[ni][0] = p00; sc[ni][1] = p01; sc[ni][2] = p10; sc[ni][3] = p11;
        }
        s0 += __shfl_xor_sync(0xffffffff, s0, 1);
        s0 += __shfl_xor_sync(0xffffffff, s0, 2);
        s1 += __shfl_xor_sync(0xffffffff, s1, 1);
        s1 += __shfl_xor_sync(0xffffffff, s1, 2);
        l0 = l0 * c0 + s0;
        l1 = l1 * c1 + s1;

        #pragma unroll
        for (int ni = 0; ni < 8; ni++) {
            oacc[ni][0] *= c0; oacc[ni][1] *= c0;
            oacc[ni][2] *= c1; oacc[ni][3] *= c1;
        }
        #pragma unroll
        for (int kki = 0; kki < 4; kki++) {
            int ni0 = 2 * kki;
            unsigned af2[4];
            af2[0] = packh2(sc[ni0][0],     sc[ni0][1]);
            af2[1] = packh2(sc[ni0][2],     sc[ni0][3]);
            af2[2] = packh2(sc[ni0 + 1][0], sc[ni0 + 1][1]);
            af2[3] = packh2(sc[ni0 + 1][2], sc[ni0 + 1][3]);
            #pragma unroll
            for (int g = 0; g < 4; g++) {
                unsigned bf[4];
                ldsm4t(bf, vB + (unsigned)((kki * 16) * FSTR + g * 16 + offV) * 2u);
                mma16(oacc[2 * g],     af2, bf[0], bf[2]);
                mma16(oacc[2 * g + 1], af2, bf[1], bf[3]);
            }
        }
        __syncthreads();
    }

    {
        int q = lane >> 2, r2c = (lane & 3) * 2;
        float i0 = 1.0f / l0, i1 = 1.0f / l1;
        int row0 = qrow0 + wm + q;
        #pragma unroll
        for (int ni = 0; ni < 8; ni++) {
            int col = h * 64 + ni * 8 + r2c;
            size_t g0 = (size_t)(b * SEQ + row0) * D_MODEL + col;
            size_t g1 = (size_t)(b * SEQ + row0 + 8) * D_MODEL + col;
            ((__half2*)O)[g0 >> 1] = __floats2half2_rn(oacc[ni][0] * i0, oacc[ni][1] * i0);
            ((__half2*)O)[g1 >> 1] = __floats2half2_rn(oacc[ni][2] * i1, oacc[ni][3] * i1);
        }
    }
}

// ---------------------------------------------------------------------------
// Reductions / LN
// ---------------------------------------------------------------------------
__device__ __forceinline__ float block_reduce_sum(float val, float* sdata) {
    int t = threadIdx.x;
    #pragma unroll
    for (int off = 16; off > 0; off >>= 1)
        val += __shfl_down_sync(0xffffffff, val, off);
    if ((t & 31) == 0) sdata[t >> 5] = val;
    __syncthreads();
    if (t < 32) {
        float v = (t < 8) ? sdata[t] : 0.0f;
        #pragma unroll
        for (int off = 4; off > 0; off >>= 1)
            v += __shfl_down_sync(0xffffffff, v, off);
        if (t == 0) sdata[0] = v;
    }
    __syncthreads();
    float r = sdata[0];
    __syncthreads();
    return r;
}

// LN; optionally also writes rows [1008,1024) of each batch to memout (new_mem)
__global__ __launch_bounds__(256)
void ln_kernel(const float* __restrict__ x, const float* __restrict__ g,
               const float* __restrict__ bb, float* __restrict__ outf,
               __half* __restrict__ outh, float* __restrict__ memout) {
    __shared__ float sdata[32];
    int row = blockIdx.x;
    int t = threadIdx.x;
    const float* xr = x + (size_t)row * D_MODEL;
    float v[4];
    #pragma unroll
    for (int i = 0; i < 4; i++) v[i] = xr[t + 256 * i];
    float s = v[0] + v[1] + v[2] + v[3];
    float mu = block_reduce_sum(s, sdata) * (1.0f / 1024.0f);
    float sq = 0.f;
    #pragma unroll
    for (int i = 0; i < 4; i++) { float d0 = v[i] - mu; sq += d0 * d0; }
    float var = block_reduce_sum(sq, sdata) * (1.0f / 1024.0f);
    float inv = 1.0f / sqrtf(var + 1e-5f);
    int srow = row & (SEQ - 1), bidx = row >> 10;
    bool isMem = memout && (srow >= 1008);
    float* mrow = isMem ? memout + ((size_t)(bidx * 16 + srow - 1008)) * D_MODEL : nullptr;
    #pragma unroll
    for (int i = 0; i < 4; i++) {
        int c = t + 256 * i;
        float o = (v[i] - mu) * inv * g[c] + bb[c];
        outf[(size_t)row * D_MODEL + c] = o;
        if (outh) outh[(size_t)row * D_MODEL + c] = __float2half(o);
        if (isMem) mrow[c] = o;
    }
}

__global__ __launch_bounds__(256)
void ln_ln_kernel(const float* __restrict__ proj,
                  const float* __restrict__ g1, const float* __restrict__ b1,
                  const float* __restrict__ hids,
                  const float* __restrict__ g2, const float* __restrict__ b2,
                  float* __restrict__ outf, __half* __restrict__ outh) {
    __shared__ float sdata[32];
    int row = blockIdx.x;
    int t = threadIdx.x;
    const float* xr = proj + (size_t)row * D_MODEL;
    const float* hr = hids + (size_t)row * D_MODEL;
    float v[4], hv[4];
    #pragma unroll
    for (int i = 0; i < 4; i++) { v[i] = xr[t + 256 * i]; hv[i] = hr[t + 256 * i]; }
    float s = v[0] + v[1] + v[2] + v[3];
    float mu = block_reduce_sum(s, sdata) * (1.0f / 1024.0f);
    float sq = 0.f;
    #pragma unroll
    for (int i = 0; i < 4; i++) { float d0 = v[i] - mu; sq += d0 * d0; }
    float var = block_reduce_sum(sq, sdata) * (1.0f / 1024.0f);
    float inv = 1.0f / sqrtf(var + 1e-5f);
    float y[4];
    #pragma unroll
    for (int i = 0; i < 4; i++) {
        int c = t + 256 * i;
        y[i] = hv[i] + (v[i] - mu) * inv * g1[c] + b1[c];
    }
    float s2 = y[0] + y[1] + y[2] + y[3];
    float mu2 = block_reduce_sum(s2, sdata) * (1.0f / 1024.0f);
    float sq2 = 0.f;
    #pragma unroll
    for (int i = 0; i < 4; i++) { float d0 = y[i] - mu2; sq2 += d0 * d0; }
    float var2 = block_reduce_sum(sq2, sdata) * (1.0f / 1024.0f);
    float inv2 = 1.0f / sqrtf(var2 + 1e-5f);
    #pragma unroll
    for (int i = 0; i < 4; i++) {
        int c = t + 256 * i;
        float o = (y[i] - mu2) * inv2 * g2[c] + b2[c];
        outf[(size_t)row * D_MODEL + c] = o;
        outh[(size_t)row * D_MODEL + c] = __float2half(o);
    }
}

// ---------------------------------------------------------------------------
static float *s_hids0 = 0, *s_proj = 0, *s_hids = 0, *s_outattn = 0, *s_pos = 0;
static __half *s_h0h = 0, *s_qkvh = 0, *s_attnh = 0, *s_hidsh = 0, *s_outh = 0;
static __half *s_wTa = 0, *s_wTo = 0, *s_wTaow = 0, *s_wToow = 0, *s_wTff2 = 0;

static void resolve_scratch() {
    if (s_hids0) return;
    cudaGetSymbolAddress((void**)&s_hids0,   g_hids0);
    cudaGetSymbolAddress((void**)&s_proj,    g_proj);
    cudaGetSymbolAddress((void**)&s_hids,    g_hids);
    cudaGetSymbolAddress((void**)&s_outattn, g_outattn);
    cudaGetSymbolAddress((void**)&s_pos,     g_pos);
    cudaGetSymbolAddress((void**)&s_h0h,     g_h0h);
    cudaGetSymbolAddress((void**)&s_qkvh,    g_qkvh);
    cudaGetSymbolAddress((void**)&s_attnh,   g_attnh);
    cudaGetSymbolAddress((void**)&s_hidsh,   g_hidsh);
    cudaGetSymbolAddress((void**)&s_outh,    g_outh);
    cudaGetSymbolAddress((void**)&s_wTa,     g_wTa);
    cudaGetSymbolAddress((void**)&s_wTo,     g_wTo);
    cudaGetSymbolAddress((void**)&s_wTaow,   g_wTaow);
    cudaGetSymbolAddress((void**)&s_wToow,   g_wToow);
    cudaGetSymbolAddress((void**)&s_wTff2,   g_wTff2);
    cudaFuncSetAttribute(gemm_h<false>, cudaFuncAttributeMaxDynamicSharedMemorySize, GSMEM);
    cudaFuncSetAttribute(gemm_h<true>,  cudaFuncAttributeMaxDynamicSharedMemorySize, GSMEM);
    cudaFuncSetAttribute(flash_h, cudaFuncAttributeMaxDynamicSharedMemorySize, FA_SMEM);
}

static void run_attention(const __half* xh, const __half* wT, int extraFlag) {
    gemm_h<true><<<dim3(24, 32), 128, GSMEM>>>(
        xh, wT, nullptr, s_qkvh, 1024, 1024, 1024, 3072);
    flash_h<<<dim3(8, BATCH * NHEAD), 256, FA_SMEM>>>(s_qkvh, s_attnh, extraFlag);
}

extern "C" void kernel_launch(void* const* d_in, const int* in_sizes, int n_in,
                              void* d_out, int out_size) {
    const int*   data  = (const int*)d_in[0];
    const float* emb   = (const float*)d_in[2];
    const float* a_qw  = (const float*)d_in[3];
    const float* a_kvw = (const float*)d_in[4];
    const float* a_ow  = (const float*)d_in[5];
    const float* a_g   = (const float*)d_in[6];
    const float* a_b   = (const float*)d_in[7];
    const float* o_qw  = (const float*)d_in[16];
    const float* o_kvw = (const float*)d_in[17];
    const float* o_ow  = (const float*)d_in[18];
    const float* o_g   = (const float*)d_in[19];
    const float* o_b   = (const float*)d_in[20];
    const float* ff2_w = (const float*)d_in[21];
    const float* ln1_g = (const float*)d_in[22];
    const float* ln1_b = (const float*)d_in[23];
    const float* ln2_g = (const float*)d_in[24];
    const float* ln2_b = (const float*)d_in[25];
    float* out = (float*)d_out;

    resolve_scratch();

    TpArgs tp;
    tp.src[0] = a_qw;          tp.dst[0] = s_wTa;               tp.ld[0] = 1024;
    tp.src[1] = a_kvw;         tp.dst[1] = s_wTa + 1024*1024;   tp.ld[1] = 2048;
    tp.src[2] = a_kvw + 1024;  tp.dst[2] = s_wTa + 2*1024*1024; tp.ld[2] = 2048;
    tp.src[3] = o_qw;          tp.dst[3] = s_wTo;               tp.ld[3] = 1024;
    tp.src[4] = o_kvw;         tp.dst[4] = s_wTo + 1024*1024;   tp.ld[4] = 2048;
    tp.src[5] = o_kvw + 1024;  tp.dst[5] = s_wTo + 2*1024*1024; tp.ld[5] = 2048;
    tp.src[6] = a_ow;          tp.dst[6] = s_wTaow;             tp.ld[6] = 1024;
    tp.src[7] = o_ow;          tp.dst[7] = s_wToow;             tp.ld[7] = 1024;
    tp.src[8] = ff2_w;         tp.dst[8] = s_wTff2;             tp.ld[8] = 1024;
    transpose_h_kernel<<<dim3(32, 32, 9), dim3(32, 8)>>>(tp);

    pos_kernel<<<(SEQ * D_MODEL) / 256, 256>>>(s_pos);
    embed_kernel<<<OUT_MAIN / 256, 256>>>(data, emb, s_pos, s_hids0, s_h0h);

    // self attention (layer)
    run_attention(s_h0h, s_wTa, 0);
    gemm_h<false><<<dim3(8, 32), 128, GSMEM>>>(
        s_attnh, s_wTaow, s_hids0, s_proj, 1024, 1024, 1024, 1024);
    // LN + fused new_mem extraction (rows 1008..1023 per batch)
    ln_kernel<<<MROWS, 256>>>(s_proj, a_g, a_b, s_hids, s_hidsh, out + OUT_MAIN);

    // OutputAttn (keys >= 1008 double-weighted)
    run_attention(s_hidsh, s_wTo, 1);
    gemm_h<false><<<dim3(8, 32), 128, GSMEM>>>(
        s_attnh, s_wToow, s_hids, s_proj, 1024, 1024, 1024, 1024);
    ln_ln_kernel<<<MROWS, 256>>>(s_proj, o_g, o_b, s_hids, ln1_g, ln1_b, s_outattn, s_outh);

    gemm_h<false><<<dim3(8, 32), 128, GSMEM>>>(
        s_outh, s_wTff2, s_outattn, s_proj, 1024, 1024, 1024, 1024);
    ln_kernel<<<MROWS, 256>>>(s_proj, ln2_g, ln2_b, out, nullptr, nullptr);
}